// round 2
// baseline (speedup 1.0000x reference)
#include <cuda_runtime.h>
#include <cuda_bf16.h>

// Problem constants
#define Bq 2
#define Tq 512
#define Sq 2048
#define Hq 768
#define Lq 32
#define NHq 12
#define HD 64
#define IM 3072
#define NSPAN (Bq*Sq)          // 4096
#define NTOK  (Bq*Tq)          // 1024

// -------------------- device scratch (no allocations allowed) --------------------
__device__ float g_q[Hq];                       // projected query (768)
__device__ float g_KV[(size_t)NTOK * 2 * Hq];   // [1024][1536]  K|V per token
__device__ float g_ctx[(size_t)NSPAN * Hq];     // attention context
__device__ float g_pre1[(size_t)NSPAN * Hq];    // attn_out + dummy_query (pre-LN1)
__device__ float g_x1[(size_t)NSPAN * Hq];      // LN1 output
__device__ float g_h1[(size_t)NSPAN * IM];      // FFN hidden
__device__ float g_pre2[(size_t)NSPAN * Hq];    // ffn + x1 (pre-LN2)
__device__ unsigned char g_mask[NSPAN];         // canonical 0/1 span mask

// -------------------- mask dtype sniffing + conversion --------------------
// The harness widens bool arrays to an unknown dtype (int32 / float32 / uint8).
// Detect from the bit patterns of the first 256 dwords, then convert to bytes.
__global__ void mask_conv_k(const void* __restrict__ raw) {
    __shared__ int notInt, notFloat;
    const int t = threadIdx.x;
    if (t == 0) { notInt = 0; notFloat = 0; }
    __syncthreads();
    {
        const unsigned int v = ((const unsigned int*)raw)[t];   // t in [0,256)
        if (v != 0u && v != 1u) notInt = 1;
        if (v != 0u && v != 0x3F800000u) notFloat = 1;
    }
    __syncthreads();
    const int mode = (!notInt) ? 0 : ((!notFloat) ? 1 : 2);  // 0=int32 1=f32 2=u8
    for (int i = t; i < NSPAN; i += 256) {
        unsigned char m;
        if (mode == 0)      m = (((const int*)raw)[i] != 0);
        else if (mode == 1) m = (((const float*)raw)[i] != 0.f);
        else                m = (((const unsigned char*)raw)[i] != 0);
        g_mask[i] = m;
    }
}

// -------------------- q projection --------------------
__global__ void compute_q_k(const float* __restrict__ dq,
                            const float* __restrict__ W,   // in_proj_w rows 0..767
                            const float* __restrict__ b) {
    int i = blockIdx.x * blockDim.x + threadIdx.x;
    if (i < Hq) {
        float s = b[i];
        const float* w = W + (size_t)i * Hq;
        #pragma unroll 8
        for (int h = 0; h < Hq; h++) s = fmaf(dq[h], w[h], s);
        g_q[i] = s;
    }
}

// -------------------- generic tiled SGEMM:  C = A(MxK) * B^T(NxK rows) + epi --------------------
// MODE_A: 0 = plain A ; 1 = A[m,k] = token_reps[m,k] + pe[m%512, k]
// EPI:    0 = +bias ; 1 = +bias+resvec[n] ; 2 = relu(+bias) ; 3 = +bias+resmat[m,n]
#define BM 128
#define BN 128
#define BKk 8
#define TM 8
#define TN 8

template<int MODE_A, int EPI>
__global__ __launch_bounds__(256)
void sgemm_k(const float* __restrict__ A, const float* __restrict__ B,
             const float* __restrict__ bias, const float* __restrict__ resvec,
             const float* __restrict__ resmat, float* __restrict__ C,
             int M, int N, int K, const float* __restrict__ pe) {
    __shared__ float As[BKk][BM];
    __shared__ float Bs[BKk][BN];
    const int tid = threadIdx.x;
    const int bm = blockIdx.y * BM;
    const int bn = blockIdx.x * BN;
    const int tx = tid & 15;
    const int ty = tid >> 4;
    const int lrow = tid >> 1;          // 0..127
    const int lcol = (tid & 1) * 4;     // 0 or 4

    float acc[TM][TN];
    #pragma unroll
    for (int i = 0; i < TM; i++)
        #pragma unroll
        for (int j = 0; j < TN; j++) acc[i][j] = 0.f;

    const float* aptr = A + (size_t)(bm + lrow) * K + lcol;
    const float* bptr = B + (size_t)(bn + lrow) * K + lcol;
    const float* pptr = nullptr;
    if (MODE_A == 1) pptr = pe + (size_t)((bm + lrow) & (Tq - 1)) * K + lcol;

    for (int k0 = 0; k0 < K; k0 += BKk) {
        float4 av = *(const float4*)(aptr + k0);
        if (MODE_A == 1) {
            float4 pv = *(const float4*)(pptr + k0);
            av.x += pv.x; av.y += pv.y; av.z += pv.z; av.w += pv.w;
        }
        As[lcol + 0][lrow] = av.x; As[lcol + 1][lrow] = av.y;
        As[lcol + 2][lrow] = av.z; As[lcol + 3][lrow] = av.w;

        float4 bv = *(const float4*)(bptr + k0);
        Bs[lcol + 0][lrow] = bv.x; Bs[lcol + 1][lrow] = bv.y;
        Bs[lcol + 2][lrow] = bv.z; Bs[lcol + 3][lrow] = bv.w;
        __syncthreads();

        #pragma unroll
        for (int k = 0; k < BKk; k++) {
            float ra[TM], rb[TN];
            #pragma unroll
            for (int i = 0; i < TM; i++) ra[i] = As[k][ty * TM + i];
            #pragma unroll
            for (int j = 0; j < TN; j++) rb[j] = Bs[k][tx * TN + j];
            #pragma unroll
            for (int i = 0; i < TM; i++)
                #pragma unroll
                for (int j = 0; j < TN; j++)
                    acc[i][j] = fmaf(ra[i], rb[j], acc[i][j]);
        }
        __syncthreads();
    }

    #pragma unroll
    for (int i = 0; i < TM; i++) {
        const int m = bm + ty * TM + i;
        #pragma unroll
        for (int j = 0; j < TN; j++) {
            const int n = bn + tx * TN + j;
            float v = acc[i][j] + bias[n];
            if (EPI == 1) v += resvec[n];
            if (EPI == 2) v = fmaxf(v, 0.f);
            if (EPI == 3) v += resmat[(size_t)m * N + n];
            C[(size_t)m * N + n] = v;
        }
    }
}

// -------------------- span attention (single query, 12 heads, <=32 keys) --------------------
__global__ __launch_bounds__(256)
void attn_k(const int* __restrict__ span_ids) {
    const int sp = blockIdx.x;            // 0..4095
    const int b = sp >> 11;               // /2048
    const int tid = threadIdx.x;
    __shared__ float sq[Hq];
    __shared__ float sc[NHq][Lq];

    if (!g_mask[sp]) {
        for (int i = tid; i < Hq; i += 256) g_ctx[(size_t)sp * Hq + i] = 0.f;
        return;
    }
    const int start = span_ids[sp * 2 + 0];
    int len = span_ids[sp * 2 + 1] - start;
    if (len > Lq) len = Lq;
    if (len < 1) len = 1;

    for (int i = tid; i < Hq; i += 256) sq[i] = g_q[i];
    __syncthreads();

    // scores: 12 heads x 32 positions, 64-d dot products
    const float* kvb = g_KV + (size_t)(b * Tq + start) * (2 * Hq);
    for (int idx = tid; idx < NHq * Lq; idx += 256) {
        const int n = idx >> 5, l = idx & 31;
        float s = -1e30f;
        if (l < len) {
            const float4* kr = (const float4*)(kvb + (size_t)l * (2 * Hq) + n * HD);
            const float4* qr = (const float4*)(sq + n * HD);
            float a = 0.f;
            #pragma unroll
            for (int j = 0; j < 16; j++) {
                float4 k4 = kr[j], q4 = qr[j];
                a = fmaf(k4.x, q4.x, a); a = fmaf(k4.y, q4.y, a);
                a = fmaf(k4.z, q4.z, a); a = fmaf(k4.w, q4.w, a);
            }
            s = a * 0.125f;  // 1/sqrt(64)
        }
        sc[n][l] = s;
    }
    __syncthreads();

    // softmax per head (cheap: 12 heads x <=32 entries)
    if (tid < NHq) {
        float mx = -1e30f;
        for (int l = 0; l < len; l++) mx = fmaxf(mx, sc[tid][l]);
        float sum = 0.f;
        for (int l = 0; l < Lq; l++) {
            float e = (l < len) ? __expf(sc[tid][l] - mx) : 0.f;
            sc[tid][l] = e; sum += e;
        }
        float inv = 1.f / sum;
        for (int l = 0; l < Lq; l++) sc[tid][l] *= inv;
    }
    __syncthreads();

    // ctx[d] = sum_l attn[head(d)][l] * V[l, d]
    const float* vb = kvb + Hq;
    for (int d = tid; d < Hq; d += 256) {
        const int n = d >> 6;
        float a = 0.f;
        for (int l = 0; l < len; l++)
            a = fmaf(sc[n][l], vb[(size_t)l * (2 * Hq) + d], a);
        g_ctx[(size_t)sp * Hq + d] = a;
    }
}

// -------------------- LayerNorm (row = 768, block = 256 threads) --------------------
template<bool MASKED>
__global__ __launch_bounds__(256)
void ln_k(const float* __restrict__ X, const float* __restrict__ g,
          const float* __restrict__ bt, float* __restrict__ Y) {
    const int row = blockIdx.x;
    const int tid = threadIdx.x;
    const float* x = X + (size_t)row * Hq;
    __shared__ float red[8];
    __shared__ float sval;

    float v0 = x[tid], v1 = x[tid + 256], v2 = x[tid + 512];
    float s = v0 + v1 + v2;
    #pragma unroll
    for (int o = 16; o > 0; o >>= 1) s += __shfl_down_sync(0xffffffffu, s, o);
    if ((tid & 31) == 0) red[tid >> 5] = s;
    __syncthreads();
    if (tid == 0) {
        float t = 0.f;
        #pragma unroll
        for (int w = 0; w < 8; w++) t += red[w];
        sval = t * (1.f / Hq);
    }
    __syncthreads();
    const float mean = sval;
    const float d0 = v0 - mean, d1 = v1 - mean, d2 = v2 - mean;
    float vs = d0 * d0 + d1 * d1 + d2 * d2;
    __syncthreads();
    #pragma unroll
    for (int o = 16; o > 0; o >>= 1) vs += __shfl_down_sync(0xffffffffu, vs, o);
    if ((tid & 31) == 0) red[tid >> 5] = vs;
    __syncthreads();
    if (tid == 0) {
        float t = 0.f;
        #pragma unroll
        for (int w = 0; w < 8; w++) t += red[w];
        sval = rsqrtf(t * (1.f / Hq) + 1e-5f);
    }
    __syncthreads();
    const float rstd = sval;
    float m = 1.f;
    if (MASKED) m = g_mask[row] ? 1.f : 0.f;
    float* y = Y + (size_t)row * Hq;
    y[tid]       = (d0 * rstd * g[tid]       + bt[tid])       * m;
    y[tid + 256] = (d1 * rstd * g[tid + 256] + bt[tid + 256]) * m;
    y[tid + 512] = (d2 * rstd * g[tid + 512] + bt[tid + 512]) * m;
}

// -------------------- launch --------------------
extern "C" void kernel_launch(void* const* d_in, const int* in_sizes, int n_in,
                              void* d_out, int out_size) {
    const float* token_reps = (const float*)d_in[0];
    const int* span_ids     = (const int*)d_in[1];
    const void* span_masks  = (const void*)d_in[2];
    // `pooling` scalar may or may not be passed as an input; detect via size==1
    int k = 3;
    if (n_in >= 16 && in_sizes[3] == 1) k = 4;
    const float* pe          = (const float*)d_in[k + 0];
    const float* dummy_query = (const float*)d_in[k + 1];
    const float* in_proj_w   = (const float*)d_in[k + 2];
    const float* in_proj_b   = (const float*)d_in[k + 3];
    const float* out_proj_w  = (const float*)d_in[k + 4];
    const float* out_proj_b  = (const float*)d_in[k + 5];
    const float* norm_g      = (const float*)d_in[k + 6];
    const float* norm_b      = (const float*)d_in[k + 7];
    const float* ffn_w1      = (const float*)d_in[k + 8];
    const float* ffn_b1      = (const float*)d_in[k + 9];
    const float* ffn_w2      = (const float*)d_in[k + 10];
    const float* ffn_b2      = (const float*)d_in[k + 11];

    float *p_KV, *p_ctx, *p_pre1, *p_x1, *p_h1, *p_pre2;
    cudaGetSymbolAddress((void**)&p_KV,   g_KV);
    cudaGetSymbolAddress((void**)&p_ctx,  g_ctx);
    cudaGetSymbolAddress((void**)&p_pre1, g_pre1);
    cudaGetSymbolAddress((void**)&p_x1,   g_x1);
    cudaGetSymbolAddress((void**)&p_h1,   g_h1);
    cudaGetSymbolAddress((void**)&p_pre2, g_pre2);

    // 0. canonicalize span mask (dtype sniff: int32 / float32 / uint8)
    mask_conv_k<<<1, 256>>>(span_masks);

    // 1. q = dummy_query @ Wq^T + bq
    compute_q_k<<<3, 256>>>(dummy_query, in_proj_w, in_proj_b);

    // 2. KV = (token_reps + pe) @ [Wk;Wv]^T + [bk;bv]   (M=1024, N=1536, K=768)
    sgemm_k<1, 0><<<dim3(1536 / BN, NTOK / BM), 256>>>(
        token_reps, in_proj_w + (size_t)Hq * Hq, in_proj_b + Hq,
        nullptr, nullptr, p_KV, NTOK, 2 * Hq, Hq, pe);

    // 3. per-span attention -> ctx
    attn_k<<<NSPAN, 256>>>(span_ids);

    // 4. pre1 = ctx @ Wout^T + bout + dummy_query   (M=4096, N=768, K=768)
    sgemm_k<0, 1><<<dim3(Hq / BN, NSPAN / BM), 256>>>(
        p_ctx, out_proj_w, out_proj_b, dummy_query, nullptr, p_pre1,
        NSPAN, Hq, Hq, nullptr);

    // 5. x1 = LN(pre1)
    ln_k<false><<<NSPAN, 256>>>(p_pre1, norm_g, norm_b, p_x1);

    // 6. h1 = relu(x1 @ W1^T + b1)   (M=4096, N=3072, K=768)
    sgemm_k<0, 2><<<dim3(IM / BN, NSPAN / BM), 256>>>(
        p_x1, ffn_w1, ffn_b1, nullptr, nullptr, p_h1, NSPAN, IM, Hq, nullptr);

    // 7. pre2 = h1 @ W2^T + b2 + x1   (M=4096, N=768, K=3072)
    sgemm_k<0, 3><<<dim3(Hq / BN, NSPAN / BM), 256>>>(
        p_h1, ffn_w2, ffn_b2, nullptr, p_x1, p_pre2, NSPAN, Hq, IM, nullptr);

    // 8. out = LN(pre2) * mask
    ln_k<true><<<NSPAN, 256>>>(p_pre2, norm_g, norm_b, (float*)d_out);
}

// round 4
// speedup vs baseline: 1.6019x; 1.6019x over previous
#include <cuda_runtime.h>
#include <cuda_bf16.h>
#include <cstdint>

// Problem constants
#define Bq 2
#define Tq 512
#define Sq 2048
#define Hq 768
#define Lq 32
#define NHq 12
#define HD 64
#define IM 3072
#define NSPAN (Bq*Sq)          // 4096
#define NTOK  (Bq*Tq)          // 1024

typedef __nv_bfloat16 bf16;

// -------------------- device scratch --------------------
__device__ float g_q[Hq];
__device__ float g_KV[(size_t)NTOK * 2 * Hq];
__device__ bf16  g_tokpe_h[(size_t)NTOK * Hq], g_tokpe_l[(size_t)NTOK * Hq];
__device__ bf16  g_wkv_h[(size_t)2 * Hq * Hq], g_wkv_l[(size_t)2 * Hq * Hq];
__device__ bf16  g_wout_h[(size_t)Hq * Hq],   g_wout_l[(size_t)Hq * Hq];
__device__ bf16  g_w1_h[(size_t)IM * Hq],     g_w1_l[(size_t)IM * Hq];
__device__ bf16  g_w2_h[(size_t)Hq * IM],     g_w2_l[(size_t)Hq * IM];
__device__ bf16  g_ctx_h[(size_t)NSPAN * Hq], g_ctx_l[(size_t)NSPAN * Hq];
__device__ float g_pre1[(size_t)NSPAN * Hq];
__device__ float g_x1[(size_t)NSPAN * Hq];
__device__ bf16  g_x1_h[(size_t)NSPAN * Hq],  g_x1_l[(size_t)NSPAN * Hq];
__device__ bf16  g_h1_h[(size_t)NSPAN * IM],  g_h1_l[(size_t)NSPAN * IM];
__device__ float g_pre2[(size_t)NSPAN * Hq];
__device__ unsigned char g_mask[NSPAN];

// -------------------- helpers --------------------
__device__ __forceinline__ uint32_t smem_u32(const void* p) {
    uint32_t a;
    asm("{ .reg .u64 t; cvta.to.shared.u64 t, %1; cvt.u32.u64 %0, t; }" : "=r"(a) : "l"(p));
    return a;
}
#define SW128(o) ((o) ^ (((o) >> 3) & 0x70))

__device__ __forceinline__ void ldm_x4(uint32_t& r0, uint32_t& r1, uint32_t& r2, uint32_t& r3,
                                       uint32_t addr) {
    asm volatile("ldmatrix.sync.aligned.m8n8.x4.shared.b16 {%0,%1,%2,%3}, [%4];"
                 : "=r"(r0), "=r"(r1), "=r"(r2), "=r"(r3) : "r"(addr));
}
__device__ __forceinline__ void mma16816(float* d, const uint32_t* a, const uint32_t* b) {
    asm volatile(
        "mma.sync.aligned.m16n8k16.row.col.f32.bf16.bf16.f32 "
        "{%0,%1,%2,%3}, {%4,%5,%6,%7}, {%8,%9}, {%0,%1,%2,%3};"
        : "+f"(d[0]), "+f"(d[1]), "+f"(d[2]), "+f"(d[3])
        : "r"(a[0]), "r"(a[1]), "r"(a[2]), "r"(a[3]), "r"(b[0]), "r"(b[1]));
}

// -------------------- mask dtype sniffing + conversion --------------------
__global__ void mask_conv_k(const void* __restrict__ raw) {
    __shared__ int notInt, notFloat;
    const int t = threadIdx.x;
    if (t == 0) { notInt = 0; notFloat = 0; }
    __syncthreads();
    {
        const unsigned int v = ((const unsigned int*)raw)[t];
        if (v != 0u && v != 1u) notInt = 1;
        if (v != 0u && v != 0x3F800000u) notFloat = 1;
    }
    __syncthreads();
    const int mode = (!notInt) ? 0 : ((!notFloat) ? 1 : 2);
    for (int i = t; i < NSPAN; i += 256) {
        unsigned char m;
        if (mode == 0)      m = (((const int*)raw)[i] != 0);
        else if (mode == 1) m = (((const float*)raw)[i] != 0.f);
        else                m = (((const unsigned char*)raw)[i] != 0);
        g_mask[i] = m;
    }
}

// -------------------- q projection --------------------
__global__ void compute_q_k(const float* __restrict__ dq,
                            const float* __restrict__ W,
                            const float* __restrict__ b) {
    int i = blockIdx.x * blockDim.x + threadIdx.x;
    if (i < Hq) {
        float s = b[i];
        const float* w = W + (size_t)i * Hq;
        #pragma unroll 8
        for (int h = 0; h < Hq; h++) s = fmaf(dq[h], w[h], s);
        g_q[i] = s;
    }
}

// -------------------- fp32 -> bf16 hi/lo split kernels --------------------
__global__ void split_k(const float* __restrict__ in, bf16* __restrict__ hi,
                        bf16* __restrict__ lo, int n4) {
    int i = blockIdx.x * 256 + threadIdx.x;
    if (i >= n4) return;
    float4 v = ((const float4*)in)[i];
    union { bf16 b[4]; uint2 u; } H, L;
    H.b[0] = __float2bfloat16(v.x); L.b[0] = __float2bfloat16(v.x - __bfloat162float(H.b[0]));
    H.b[1] = __float2bfloat16(v.y); L.b[1] = __float2bfloat16(v.y - __bfloat162float(H.b[1]));
    H.b[2] = __float2bfloat16(v.z); L.b[2] = __float2bfloat16(v.z - __bfloat162float(H.b[2]));
    H.b[3] = __float2bfloat16(v.w); L.b[3] = __float2bfloat16(v.w - __bfloat162float(H.b[3]));
    ((uint2*)hi)[i] = H.u;
    ((uint2*)lo)[i] = L.u;
}

__global__ void tokpe_split_k(const float* __restrict__ tok, const float* __restrict__ pe,
                              bf16* __restrict__ hi, bf16* __restrict__ lo) {
    int i = blockIdx.x * 256 + threadIdx.x;
    if (i >= NTOK * Hq / 4) return;
    int e = i * 4;
    int pe_e = (e >= Tq * Hq) ? e - Tq * Hq : e;
    float4 a = *(const float4*)(tok + e);
    float4 p = *(const float4*)(pe + pe_e);
    a.x += p.x; a.y += p.y; a.z += p.z; a.w += p.w;
    union { bf16 b[4]; uint2 u; } H, L;
    H.b[0] = __float2bfloat16(a.x); L.b[0] = __float2bfloat16(a.x - __bfloat162float(H.b[0]));
    H.b[1] = __float2bfloat16(a.y); L.b[1] = __float2bfloat16(a.y - __bfloat162float(H.b[1]));
    H.b[2] = __float2bfloat16(a.z); L.b[2] = __float2bfloat16(a.z - __bfloat162float(H.b[2]));
    H.b[3] = __float2bfloat16(a.w); L.b[3] = __float2bfloat16(a.w - __bfloat162float(H.b[3]));
    ((uint2*)hi)[i] = H.u;
    ((uint2*)lo)[i] = L.u;
}

// -------------------- mma.sync bf16-split GEMM: C = A(MxK) * B^T(NxK) + epi --------------------
// EPI: 0 = +bias -> C fp32
//      1 = +bias+resvec -> C fp32
//      2 = relu(+bias) -> Ch/Cl bf16 hi/lo
//      3 = +bias+resmat -> C fp32
// CTA 128x128xBK64; 8 warps (2x4); warp tile 64x32 (4 mtiles x 4 ntiles).
// Smem tiles (16KB each): 0=Ah 1=Al 2=Bh 3=Bl; rows of 64 bf16 (128B), SW128.
#define GSMEM_BYTES 65536

template<int EPI>
__global__ __launch_bounds__(256)
void mma_gemm_k(const bf16* __restrict__ Ah, const bf16* __restrict__ Al,
                const bf16* __restrict__ Bh, const bf16* __restrict__ Bl,
                const float* __restrict__ bias, const float* __restrict__ resvec,
                const float* __restrict__ resmat,
                float* __restrict__ C, bf16* __restrict__ Ch, bf16* __restrict__ Cl,
                int M, int N, int K) {
    extern __shared__ char sm[];
    const uint32_t sb = smem_u32(sm);
    const int tid = threadIdx.x;
    const int wid = tid >> 5, lane = tid & 31;
    const int wm = wid >> 2;            // 0..1 -> m offset wm*64
    const int wn = wid & 3;             // 0..3 -> n offset wn*32
    const int bm = blockIdx.y * 128, bn = blockIdx.x * 128;

    float acc[4][4][4];
    #pragma unroll
    for (int i = 0; i < 4; i++)
        #pragma unroll
        for (int j = 0; j < 4; j++)
            #pragma unroll
            for (int r = 0; r < 4; r++) acc[i][j][r] = 0.f;

    // per-thread ldmatrix row indices (fixed across k)
    // A: lanes 0-15 -> rows base+lane (tiles 0,1), lanes 16-31 -> rows base+(lane-16), chunk+1
    const int rA_off = (lane & 15);
    const int cqA = lane >> 4;          // 0/1 -> k-chunk select
    // B: row = nbase + (lane>>4)*8 + (lane&7); chunk = kc + ((lane>>3)&1)
    const int rB_off = ((lane >> 4) << 3) + (lane & 7);
    const int cqB = (lane >> 3) & 1;

    const int NCH = K >> 6;
    for (int c = 0; c < NCH; c++) {
        const int k0 = c << 6;
        // cooperative load of 4 tiles, 128 rows x 64 bf16 each, SW128
        #pragma unroll 4
        for (int idx = tid; idx < 4096; idx += 256) {
            const int t = idx >> 10, r = (idx >> 3) & 127, j = idx & 7;
            const bf16* src;
            if (t == 0)      src = Ah + (size_t)(bm + r) * K + k0 + j * 8;
            else if (t == 1) src = Al + (size_t)(bm + r) * K + k0 + j * 8;
            else if (t == 2) src = Bh + (size_t)(bn + r) * K + k0 + j * 8;
            else             src = Bl + (size_t)(bn + r) * K + k0 + j * 8;
            uint4 v = *(const uint4*)src;
            const uint32_t off = (t << 14) | SW128((r << 7) | (j << 4));
            *(uint4*)(sm + off) = v;
        }
        __syncthreads();

        #pragma unroll
        for (int ks = 0; ks < 4; ks++) {
            const int k2 = ks * 2;
            uint32_t ah[4][4], al[4][4];
            #pragma unroll
            for (int mt = 0; mt < 4; mt++) {
                const int row = wm * 64 + mt * 16 + rA_off;
                const uint32_t ph = (uint32_t)((k2 + cqA) ^ (row & 7));
                const uint32_t base = sb + (uint32_t)(row << 7) + (ph << 4);
                ldm_x4(ah[mt][0], ah[mt][1], ah[mt][2], ah[mt][3], base);
                ldm_x4(al[mt][0], al[mt][1], al[mt][2], al[mt][3], base + 16384u);
            }
            uint32_t bh[4][2], bl[4][2];
            #pragma unroll
            for (int p = 0; p < 2; p++) {
                const int row = wn * 32 + p * 16 + rB_off;
                const uint32_t ph = (uint32_t)((k2 + cqB) ^ (row & 7));
                const uint32_t base = sb + 32768u + (uint32_t)(row << 7) + (ph << 4);
                ldm_x4(bh[p*2][0], bh[p*2][1], bh[p*2+1][0], bh[p*2+1][1], base);
                ldm_x4(bl[p*2][0], bl[p*2][1], bl[p*2+1][0], bl[p*2+1][1], base + 16384u);
            }
            #pragma unroll
            for (int mt = 0; mt < 4; mt++)
                #pragma unroll
                for (int nt = 0; nt < 4; nt++) {
                    mma16816(acc[mt][nt], ah[mt], bh[nt]);
                    mma16816(acc[mt][nt], ah[mt], bl[nt]);
                    mma16816(acc[mt][nt], al[mt], bh[nt]);
                }
        }
        __syncthreads();
    }

    // epilogue: fragment layout d0,d1 -> (m, n0),(m, n0+1); d2,d3 -> (m+8, ...)
    const int gq = lane >> 2, tq = lane & 3;
    #pragma unroll
    for (int mt = 0; mt < 4; mt++) {
        #pragma unroll
        for (int nt = 0; nt < 4; nt++) {
            const int n0 = bn + wn * 32 + nt * 8 + tq * 2;
            const float2 bz = *(const float2*)&bias[n0];
            #pragma unroll
            for (int hrow = 0; hrow < 2; hrow++) {
                const int m = bm + wm * 64 + mt * 16 + gq + hrow * 8;
                float vx = acc[mt][nt][hrow * 2 + 0] + bz.x;
                float vy = acc[mt][nt][hrow * 2 + 1] + bz.y;
                if (EPI == 1) {
                    const float2 rv = *(const float2*)&resvec[n0];
                    vx += rv.x; vy += rv.y;
                }
                if (EPI == 3) {
                    const float2 rm = *(const float2*)&resmat[(size_t)m * N + n0];
                    vx += rm.x; vy += rm.y;
                }
                if (EPI == 2) {
                    vx = fmaxf(vx, 0.f); vy = fmaxf(vy, 0.f);
                    union { bf16 b[2]; uint32_t u; } H, L;
                    H.b[0] = __float2bfloat16(vx); L.b[0] = __float2bfloat16(vx - __bfloat162float(H.b[0]));
                    H.b[1] = __float2bfloat16(vy); L.b[1] = __float2bfloat16(vy - __bfloat162float(H.b[1]));
                    *(uint32_t*)&Ch[(size_t)m * N + n0] = H.u;
                    *(uint32_t*)&Cl[(size_t)m * N + n0] = L.u;
                } else {
                    float2 o; o.x = vx; o.y = vy;
                    *(float2*)&C[(size_t)m * N + n0] = o;
                }
            }
        }
    }
}

// -------------------- span attention (outputs ctx as bf16 hi/lo) --------------------
__global__ __launch_bounds__(256)
void attn_k(const int* __restrict__ span_ids) {
    const int sp = blockIdx.x;
    const int b = sp >> 11;
    const int tid = threadIdx.x;
    __shared__ float sq[Hq];
    __shared__ float sc[NHq][Lq];

    if (!g_mask[sp]) {
        for (int i = tid; i < Hq; i += 256) {
            g_ctx_h[(size_t)sp * Hq + i] = __float2bfloat16(0.f);
            g_ctx_l[(size_t)sp * Hq + i] = __float2bfloat16(0.f);
        }
        return;
    }
    const int start = span_ids[sp * 2 + 0];
    int len = span_ids[sp * 2 + 1] - start;
    if (len > Lq) len = Lq;
    if (len < 1) len = 1;

    for (int i = tid; i < Hq; i += 256) sq[i] = g_q[i];
    __syncthreads();

    const float* kvb = g_KV + (size_t)(b * Tq + start) * (2 * Hq);
    for (int idx = tid; idx < NHq * Lq; idx += 256) {
        const int n = idx >> 5, l = idx & 31;
        float s = -1e30f;
        if (l < len) {
            const float4* kr = (const float4*)(kvb + (size_t)l * (2 * Hq) + n * HD);
            const float4* qr = (const float4*)(sq + n * HD);
            float a = 0.f;
            #pragma unroll
            for (int j = 0; j < 16; j++) {
                float4 k4 = kr[j], q4 = qr[j];
                a = fmaf(k4.x, q4.x, a); a = fmaf(k4.y, q4.y, a);
                a = fmaf(k4.z, q4.z, a); a = fmaf(k4.w, q4.w, a);
            }
            s = a * 0.125f;
        }
        sc[n][l] = s;
    }
    __syncthreads();

    if (tid < NHq) {
        float mx = -1e30f;
        for (int l = 0; l < len; l++) mx = fmaxf(mx, sc[tid][l]);
        float sum = 0.f;
        for (int l = 0; l < Lq; l++) {
            float e = (l < len) ? __expf(sc[tid][l] - mx) : 0.f;
            sc[tid][l] = e; sum += e;
        }
        float inv = 1.f / sum;
        for (int l = 0; l < Lq; l++) sc[tid][l] *= inv;
    }
    __syncthreads();

    const float* vb = kvb + Hq;
    for (int d = tid; d < Hq; d += 256) {
        const int n = d >> 6;
        float a = 0.f;
        for (int l = 0; l < len; l++)
            a = fmaf(sc[n][l], vb[(size_t)l * (2 * Hq) + d], a);
        bf16 h = __float2bfloat16(a);
        g_ctx_h[(size_t)sp * Hq + d] = h;
        g_ctx_l[(size_t)sp * Hq + d] = __float2bfloat16(a - __bfloat162float(h));
    }
}

// -------------------- LayerNorm --------------------
// MODE 0: Y fp32 + Yh/Yl bf16 hi/lo (x1)     MODE 1: Y fp32 * mask (final)
template<int MODE>
__global__ __launch_bounds__(256)
void ln_k(const float* __restrict__ X, const float* __restrict__ g,
          const float* __restrict__ bt, float* __restrict__ Y,
          bf16* __restrict__ Yh, bf16* __restrict__ Yl) {
    const int row = blockIdx.x;
    const int tid = threadIdx.x;
    const float* x = X + (size_t)row * Hq;
    __shared__ float red[8];
    __shared__ float sval;

    float v0 = x[tid], v1 = x[tid + 256], v2 = x[tid + 512];
    float s = v0 + v1 + v2;
    #pragma unroll
    for (int o = 16; o > 0; o >>= 1) s += __shfl_down_sync(0xffffffffu, s, o);
    if ((tid & 31) == 0) red[tid >> 5] = s;
    __syncthreads();
    if (tid == 0) {
        float t = 0.f;
        #pragma unroll
        for (int w = 0; w < 8; w++) t += red[w];
        sval = t * (1.f / Hq);
    }
    __syncthreads();
    const float mean = sval;
    const float d0 = v0 - mean, d1 = v1 - mean, d2 = v2 - mean;
    float vs = d0 * d0 + d1 * d1 + d2 * d2;
    __syncthreads();
    #pragma unroll
    for (int o = 16; o > 0; o >>= 1) vs += __shfl_down_sync(0xffffffffu, vs, o);
    if ((tid & 31) == 0) red[tid >> 5] = vs;
    __syncthreads();
    if (tid == 0) {
        float t = 0.f;
        #pragma unroll
        for (int w = 0; w < 8; w++) t += red[w];
        sval = rsqrtf(t * (1.f / Hq) + 1e-5f);
    }
    __syncthreads();
    const float rstd = sval;
    float m = 1.f;
    if (MODE == 1) m = g_mask[row] ? 1.f : 0.f;
    float* y = Y + (size_t)row * Hq;
    float r0 = (d0 * rstd * g[tid]       + bt[tid])       * m;
    float r1 = (d1 * rstd * g[tid + 256] + bt[tid + 256]) * m;
    float r2 = (d2 * rstd * g[tid + 512] + bt[tid + 512]) * m;
    y[tid] = r0; y[tid + 256] = r1; y[tid + 512] = r2;
    if (MODE == 0) {
        bf16 h0 = __float2bfloat16(r0), h1 = __float2bfloat16(r1), h2 = __float2bfloat16(r2);
        Yh[(size_t)row * Hq + tid]       = h0;
        Yh[(size_t)row * Hq + tid + 256] = h1;
        Yh[(size_t)row * Hq + tid + 512] = h2;
        Yl[(size_t)row * Hq + tid]       = __float2bfloat16(r0 - __bfloat162float(h0));
        Yl[(size_t)row * Hq + tid + 256] = __float2bfloat16(r1 - __bfloat162float(h1));
        Yl[(size_t)row * Hq + tid + 512] = __float2bfloat16(r2 - __bfloat162float(h2));
    }
}

// -------------------- launch --------------------
extern "C" void kernel_launch(void* const* d_in, const int* in_sizes, int n_in,
                              void* d_out, int out_size) {
    const float* token_reps = (const float*)d_in[0];
    const int* span_ids     = (const int*)d_in[1];
    const void* span_masks  = (const void*)d_in[2];
    int k = 3;
    if (n_in >= 16 && in_sizes[3] == 1) k = 4;
    const float* pe          = (const float*)d_in[k + 0];
    const float* dummy_query = (const float*)d_in[k + 1];
    const float* in_proj_w   = (const float*)d_in[k + 2];
    const float* in_proj_b   = (const float*)d_in[k + 3];
    const float* out_proj_w  = (const float*)d_in[k + 4];
    const float* out_proj_b  = (const float*)d_in[k + 5];
    const float* norm_g      = (const float*)d_in[k + 6];
    const float* norm_b      = (const float*)d_in[k + 7];
    const float* ffn_w1      = (const float*)d_in[k + 8];
    const float* ffn_b1      = (const float*)d_in[k + 9];
    const float* ffn_w2      = (const float*)d_in[k + 10];
    const float* ffn_b2      = (const float*)d_in[k + 11];

    float *p_KV, *p_pre1, *p_x1, *p_pre2;
    bf16 *p_tokpe_h, *p_tokpe_l, *p_wkv_h, *p_wkv_l, *p_wout_h, *p_wout_l;
    bf16 *p_w1_h, *p_w1_l, *p_w2_h, *p_w2_l, *p_ctx_h, *p_ctx_l;
    bf16 *p_x1_h, *p_x1_l, *p_h1_h, *p_h1_l;
    cudaGetSymbolAddress((void**)&p_KV, g_KV);
    cudaGetSymbolAddress((void**)&p_pre1, g_pre1);
    cudaGetSymbolAddress((void**)&p_x1, g_x1);
    cudaGetSymbolAddress((void**)&p_pre2, g_pre2);
    cudaGetSymbolAddress((void**)&p_tokpe_h, g_tokpe_h);
    cudaGetSymbolAddress((void**)&p_tokpe_l, g_tokpe_l);
    cudaGetSymbolAddress((void**)&p_wkv_h, g_wkv_h);
    cudaGetSymbolAddress((void**)&p_wkv_l, g_wkv_l);
    cudaGetSymbolAddress((void**)&p_wout_h, g_wout_h);
    cudaGetSymbolAddress((void**)&p_wout_l, g_wout_l);
    cudaGetSymbolAddress((void**)&p_w1_h, g_w1_h);
    cudaGetSymbolAddress((void**)&p_w1_l, g_w1_l);
    cudaGetSymbolAddress((void**)&p_w2_h, g_w2_h);
    cudaGetSymbolAddress((void**)&p_w2_l, g_w2_l);
    cudaGetSymbolAddress((void**)&p_ctx_h, g_ctx_h);
    cudaGetSymbolAddress((void**)&p_ctx_l, g_ctx_l);
    cudaGetSymbolAddress((void**)&p_x1_h, g_x1_h);
    cudaGetSymbolAddress((void**)&p_x1_l, g_x1_l);
    cudaGetSymbolAddress((void**)&p_h1_h, g_h1_h);
    cudaGetSymbolAddress((void**)&p_h1_l, g_h1_l);

    cudaFuncSetAttribute(mma_gemm_k<0>, cudaFuncAttributeMaxDynamicSharedMemorySize, GSMEM_BYTES);
    cudaFuncSetAttribute(mma_gemm_k<1>, cudaFuncAttributeMaxDynamicSharedMemorySize, GSMEM_BYTES);
    cudaFuncSetAttribute(mma_gemm_k<2>, cudaFuncAttributeMaxDynamicSharedMemorySize, GSMEM_BYTES);
    cudaFuncSetAttribute(mma_gemm_k<3>, cudaFuncAttributeMaxDynamicSharedMemorySize, GSMEM_BYTES);

    // 0. canonicalize mask; project q
    mask_conv_k<<<1, 256>>>(span_masks);
    compute_q_k<<<3, 256>>>(dummy_query, in_proj_w, in_proj_b);

    // 1. hi/lo splits of A-side (tok+pe) and all weights
    tokpe_split_k<<<(NTOK * Hq / 4 + 255) / 256, 256>>>(token_reps, pe, p_tokpe_h, p_tokpe_l);
    split_k<<<(2 * Hq * Hq / 4 + 255) / 256, 256>>>(in_proj_w + (size_t)Hq * Hq, p_wkv_h, p_wkv_l, 2 * Hq * Hq / 4);
    split_k<<<(Hq * Hq / 4 + 255) / 256, 256>>>(out_proj_w, p_wout_h, p_wout_l, Hq * Hq / 4);
    split_k<<<(IM * Hq / 4 + 255) / 256, 256>>>(ffn_w1, p_w1_h, p_w1_l, IM * Hq / 4);
    split_k<<<(Hq * IM / 4 + 255) / 256, 256>>>(ffn_w2, p_w2_h, p_w2_l, Hq * IM / 4);

    // 2. KV = (tok+pe) @ Wkv^T + bkv    (1024 x 1536 x 768) -> fp32
    mma_gemm_k<0><<<dim3(12, 8), 256, GSMEM_BYTES>>>(
        p_tokpe_h, p_tokpe_l, p_wkv_h, p_wkv_l,
        in_proj_b + Hq, nullptr, nullptr, p_KV, nullptr, nullptr,
        NTOK, 2 * Hq, Hq);

    // 3. per-span attention -> ctx hi/lo
    attn_k<<<NSPAN, 256>>>(span_ids);

    // 4. pre1 = ctx @ Wout^T + bout + dummy_query   (4096 x 768 x 768)
    mma_gemm_k<1><<<dim3(6, 32), 256, GSMEM_BYTES>>>(
        p_ctx_h, p_ctx_l, p_wout_h, p_wout_l,
        out_proj_b, dummy_query, nullptr, p_pre1, nullptr, nullptr,
        NSPAN, Hq, Hq);

    // 5. x1 = LN(pre1)  (+ hi/lo)
    ln_k<0><<<NSPAN, 256>>>(p_pre1, norm_g, norm_b, p_x1, p_x1_h, p_x1_l);

    // 6. h1 = relu(x1 @ W1^T + b1)   (4096 x 3072 x 768) -> bf16 hi/lo
    mma_gemm_k<2><<<dim3(24, 32), 256, GSMEM_BYTES>>>(
        p_x1_h, p_x1_l, p_w1_h, p_w1_l,
        ffn_b1, nullptr, nullptr, nullptr, p_h1_h, p_h1_l,
        NSPAN, IM, Hq);

    // 7. pre2 = h1 @ W2^T + b2 + x1   (4096 x 768 x 3072)
    mma_gemm_k<3><<<dim3(6, 32), 256, GSMEM_BYTES>>>(
        p_h1_h, p_h1_l, p_w2_h, p_w2_l,
        ffn_b2, nullptr, p_x1, p_pre2, nullptr, nullptr,
        NSPAN, Hq, IM);

    // 8. out = LN(pre2) * mask
    ln_k<1><<<NSPAN, 256>>>(p_pre2, norm_g, norm_b, (float*)d_out, nullptr, nullptr);
}

// round 5
// speedup vs baseline: 2.7369x; 1.7086x over previous
#include <cuda_runtime.h>
#include <cuda_bf16.h>
#include <cstdint>

// Problem constants
#define Bq 2
#define Tq 512
#define Sq 2048
#define Hq 768
#define Lq 32
#define NHq 12
#define HD 64
#define IM 3072
#define NSPAN (Bq*Sq)          // 4096
#define NTOK  (Bq*Tq)          // 1024

typedef __nv_bfloat16 bf16;

// -------------------- device scratch --------------------
__device__ float g_q[Hq];
__device__ float g_KV[(size_t)NTOK * 2 * Hq];
__device__ bf16  g_tokpe_h[(size_t)NTOK * Hq], g_tokpe_l[(size_t)NTOK * Hq];
__device__ bf16  g_wkv_h[(size_t)2 * Hq * Hq], g_wkv_l[(size_t)2 * Hq * Hq];
__device__ bf16  g_wout_h[(size_t)Hq * Hq],   g_wout_l[(size_t)Hq * Hq];
__device__ bf16  g_w1_h[(size_t)IM * Hq],     g_w1_l[(size_t)IM * Hq];
__device__ bf16  g_w2_h[(size_t)Hq * IM],     g_w2_l[(size_t)Hq * IM];
__device__ bf16  g_ctx_h[(size_t)NSPAN * Hq], g_ctx_l[(size_t)NSPAN * Hq];
__device__ float g_pre1[(size_t)NSPAN * Hq];
__device__ float g_x1[(size_t)NSPAN * Hq];
__device__ bf16  g_x1_h[(size_t)NSPAN * Hq],  g_x1_l[(size_t)NSPAN * Hq];
__device__ bf16  g_h1_h[(size_t)NSPAN * IM],  g_h1_l[(size_t)NSPAN * IM];
__device__ float g_pre2[(size_t)NSPAN * Hq];
__device__ unsigned char g_mask[NSPAN];

// -------------------- helpers --------------------
__device__ __forceinline__ uint32_t smem_u32(const void* p) {
    uint32_t a;
    asm("{ .reg .u64 t; cvta.to.shared.u64 t, %1; cvt.u32.u64 %0, t; }" : "=r"(a) : "l"(p));
    return a;
}
#define SW128(o) ((o) ^ (((o) >> 3) & 0x70))

__device__ __forceinline__ void ldm_x4(uint32_t& r0, uint32_t& r1, uint32_t& r2, uint32_t& r3,
                                       uint32_t addr) {
    asm volatile("ldmatrix.sync.aligned.m8n8.x4.shared.b16 {%0,%1,%2,%3}, [%4];"
                 : "=r"(r0), "=r"(r1), "=r"(r2), "=r"(r3) : "r"(addr));
}
__device__ __forceinline__ void mma16816(float* d, const uint32_t* a, const uint32_t* b) {
    asm volatile(
        "mma.sync.aligned.m16n8k16.row.col.f32.bf16.bf16.f32 "
        "{%0,%1,%2,%3}, {%4,%5,%6,%7}, {%8,%9}, {%0,%1,%2,%3};"
        : "+f"(d[0]), "+f"(d[1]), "+f"(d[2]), "+f"(d[3])
        : "r"(a[0]), "r"(a[1]), "r"(a[2]), "r"(a[3]), "r"(b[0]), "r"(b[1]));
}
__device__ __forceinline__ void cp16(uint32_t dst, const void* src) {
    asm volatile("cp.async.cg.shared.global [%0], [%1], 16;" :: "r"(dst), "l"(src));
}
#define CP_COMMIT() asm volatile("cp.async.commit_group;" ::: "memory")
template<int N> __device__ __forceinline__ void cp_wait() {
    asm volatile("cp.async.wait_group %0;" :: "n"(N) : "memory");
}

// -------------------- mask dtype sniffing + conversion --------------------
__global__ void mask_conv_k(const void* __restrict__ raw) {
    __shared__ int notInt, notFloat;
    const int t = threadIdx.x;
    if (t == 0) { notInt = 0; notFloat = 0; }
    __syncthreads();
    {
        const unsigned int v = ((const unsigned int*)raw)[t];
        if (v != 0u && v != 1u) notInt = 1;
        if (v != 0u && v != 0x3F800000u) notFloat = 1;
    }
    __syncthreads();
    const int mode = (!notInt) ? 0 : ((!notFloat) ? 1 : 2);
    for (int i = t; i < NSPAN; i += 256) {
        unsigned char m;
        if (mode == 0)      m = (((const int*)raw)[i] != 0);
        else if (mode == 1) m = (((const float*)raw)[i] != 0.f);
        else                m = (((const unsigned char*)raw)[i] != 0);
        g_mask[i] = m;
    }
}

// -------------------- q projection --------------------
__global__ void compute_q_k(const float* __restrict__ dq,
                            const float* __restrict__ W,
                            const float* __restrict__ b) {
    int i = blockIdx.x * blockDim.x + threadIdx.x;
    if (i < Hq) {
        float s = b[i];
        const float* w = W + (size_t)i * Hq;
        #pragma unroll 8
        for (int h = 0; h < Hq; h++) s = fmaf(dq[h], w[h], s);
        g_q[i] = s;
    }
}

// -------------------- fp32 -> bf16 hi/lo split kernels --------------------
__global__ void split_k(const float* __restrict__ in, bf16* __restrict__ hi,
                        bf16* __restrict__ lo, int n4) {
    int i = blockIdx.x * 256 + threadIdx.x;
    if (i >= n4) return;
    float4 v = ((const float4*)in)[i];
    union { bf16 b[4]; uint2 u; } H, L;
    H.b[0] = __float2bfloat16(v.x); L.b[0] = __float2bfloat16(v.x - __bfloat162float(H.b[0]));
    H.b[1] = __float2bfloat16(v.y); L.b[1] = __float2bfloat16(v.y - __bfloat162float(H.b[1]));
    H.b[2] = __float2bfloat16(v.z); L.b[2] = __float2bfloat16(v.z - __bfloat162float(H.b[2]));
    H.b[3] = __float2bfloat16(v.w); L.b[3] = __float2bfloat16(v.w - __bfloat162float(H.b[3]));
    ((uint2*)hi)[i] = H.u;
    ((uint2*)lo)[i] = L.u;
}

__global__ void tokpe_split_k(const float* __restrict__ tok, const float* __restrict__ pe,
                              bf16* __restrict__ hi, bf16* __restrict__ lo) {
    int i = blockIdx.x * 256 + threadIdx.x;
    if (i >= NTOK * Hq / 4) return;
    int e = i * 4;
    int pe_e = (e >= Tq * Hq) ? e - Tq * Hq : e;
    float4 a = *(const float4*)(tok + e);
    float4 p = *(const float4*)(pe + pe_e);
    a.x += p.x; a.y += p.y; a.z += p.z; a.w += p.w;
    union { bf16 b[4]; uint2 u; } H, L;
    H.b[0] = __float2bfloat16(a.x); L.b[0] = __float2bfloat16(a.x - __bfloat162float(H.b[0]));
    H.b[1] = __float2bfloat16(a.y); L.b[1] = __float2bfloat16(a.y - __bfloat162float(H.b[1]));
    H.b[2] = __float2bfloat16(a.z); L.b[2] = __float2bfloat16(a.z - __bfloat162float(H.b[2]));
    H.b[3] = __float2bfloat16(a.w); L.b[3] = __float2bfloat16(a.w - __bfloat162float(H.b[3]));
    ((uint2*)hi)[i] = H.u;
    ((uint2*)lo)[i] = L.u;
}

// -------------------- mma.sync bf16-split GEMM: C = A(MxK) * B^T(NxK) + epi --------------------
// 3-stage cp.async pipeline. CTA 128x128xBK64; 8 warps (2x4); warp tile 64x32.
// Per stage (64KB): 0=Ah 1=Al 2=Bh 3=Bl; rows of 64 bf16 (128B), SW128.
// EPI: 0 = +bias ; 1 = +bias+resvec ; 2 = relu(+bias) -> bf16 hi/lo ; 3 = +bias+resmat
#define STAGE_BYTES 65536
#define NSTAGE 3
#define GSMEM_BYTES (STAGE_BYTES * NSTAGE)

template<int EPI>
__global__ __launch_bounds__(256, 1)
void mma_gemm_k(const bf16* __restrict__ Ah, const bf16* __restrict__ Al,
                const bf16* __restrict__ Bh, const bf16* __restrict__ Bl,
                const float* __restrict__ bias, const float* __restrict__ resvec,
                const float* __restrict__ resmat,
                float* __restrict__ C, bf16* __restrict__ Ch, bf16* __restrict__ Cl,
                int M, int N, int K) {
    extern __shared__ char sm[];
    const uint32_t sb = smem_u32(sm);
    const int tid = threadIdx.x;
    const int wid = tid >> 5, lane = tid & 31;
    const int wm = wid >> 2;            // 0..1 -> m offset wm*64
    const int wn = wid & 3;             // 0..3 -> n offset wn*32
    const int bm = blockIdx.y * 128, bn = blockIdx.x * 128;

    float acc[4][4][4];
    #pragma unroll
    for (int i = 0; i < 4; i++)
        #pragma unroll
        for (int j = 0; j < 4; j++)
            #pragma unroll
            for (int r = 0; r < 4; r++) acc[i][j][r] = 0.f;

    // per-thread ldmatrix row indices
    const int rA_off = (lane & 15);
    const int cqA = lane >> 4;
    const int rB_off = ((lane >> 4) << 3) + (lane & 7);
    const int cqB = (lane >> 3) & 1;

    // precomputed per-thread load slots: 16 cp.async per thread per chunk
    const int l_t = tid >> 6;                  // tile 0..3 handled by this quarter? no:
    // simpler: idx = tid + 256*q, q in [0,16): t = idx>>10, r = (idx>>3)&127, j = idx&7
    const int NCH = K >> 6;

    auto issue_chunk = [&](int c) {
        const int k0 = c << 6;
        const uint32_t sbase = sb + (uint32_t)(c % NSTAGE) * STAGE_BYTES;
        #pragma unroll
        for (int q = 0; q < 16; q++) {
            const int idx = tid + (q << 8);
            const int t = idx >> 10, r = (idx >> 3) & 127, j = idx & 7;
            const bf16* src;
            if (t == 0)      src = Ah + (size_t)(bm + r) * K + k0 + j * 8;
            else if (t == 1) src = Al + (size_t)(bm + r) * K + k0 + j * 8;
            else if (t == 2) src = Bh + (size_t)(bn + r) * K + k0 + j * 8;
            else             src = Bl + (size_t)(bn + r) * K + k0 + j * 8;
            const uint32_t off = (t << 14) | SW128((r << 7) | (j << 4));
            cp16(sbase + off, src);
        }
        CP_COMMIT();
    };

    issue_chunk(0);
    issue_chunk(1);

    for (int c = 0; c < NCH; c++) {
        cp_wait<1>();
        __syncthreads();
        const uint32_t stage = sb + (uint32_t)(c % NSTAGE) * STAGE_BYTES;

        #pragma unroll
        for (int ks = 0; ks < 4; ks++) {
            const int k2 = ks * 2;
            uint32_t ah[4][4], al[4][4];
            #pragma unroll
            for (int mt = 0; mt < 4; mt++) {
                const int row = wm * 64 + mt * 16 + rA_off;
                const uint32_t ph = (uint32_t)((k2 + cqA) ^ (row & 7));
                const uint32_t base = stage + (uint32_t)(row << 7) + (ph << 4);
                ldm_x4(ah[mt][0], ah[mt][1], ah[mt][2], ah[mt][3], base);
                ldm_x4(al[mt][0], al[mt][1], al[mt][2], al[mt][3], base + 16384u);
            }
            uint32_t bh[4][2], bl[4][2];
            #pragma unroll
            for (int p = 0; p < 2; p++) {
                const int row = wn * 32 + p * 16 + rB_off;
                const uint32_t ph = (uint32_t)((k2 + cqB) ^ (row & 7));
                const uint32_t base = stage + 32768u + (uint32_t)(row << 7) + (ph << 4);
                ldm_x4(bh[p*2][0], bh[p*2][1], bh[p*2+1][0], bh[p*2+1][1], base);
                ldm_x4(bl[p*2][0], bl[p*2][1], bl[p*2+1][0], bl[p*2+1][1], base + 16384u);
            }
            #pragma unroll
            for (int mt = 0; mt < 4; mt++)
                #pragma unroll
                for (int nt = 0; nt < 4; nt++) {
                    mma16816(acc[mt][nt], ah[mt], bh[nt]);
                    mma16816(acc[mt][nt], ah[mt], bl[nt]);
                    mma16816(acc[mt][nt], al[mt], bh[nt]);
                }
        }
        __syncthreads();
        if (c + 2 < NCH) issue_chunk(c + 2);
    }

    // epilogue
    const int gq = lane >> 2, tq = lane & 3;
    #pragma unroll
    for (int mt = 0; mt < 4; mt++) {
        #pragma unroll
        for (int nt = 0; nt < 4; nt++) {
            const int n0 = bn + wn * 32 + nt * 8 + tq * 2;
            const float2 bz = *(const float2*)&bias[n0];
            #pragma unroll
            for (int hrow = 0; hrow < 2; hrow++) {
                const int m = bm + wm * 64 + mt * 16 + gq + hrow * 8;
                float vx = acc[mt][nt][hrow * 2 + 0] + bz.x;
                float vy = acc[mt][nt][hrow * 2 + 1] + bz.y;
                if (EPI == 1) {
                    const float2 rv = *(const float2*)&resvec[n0];
                    vx += rv.x; vy += rv.y;
                }
                if (EPI == 3) {
                    const float2 rm = *(const float2*)&resmat[(size_t)m * N + n0];
                    vx += rm.x; vy += rm.y;
                }
                if (EPI == 2) {
                    vx = fmaxf(vx, 0.f); vy = fmaxf(vy, 0.f);
                    union { bf16 b[2]; uint32_t u; } H, L;
                    H.b[0] = __float2bfloat16(vx); L.b[0] = __float2bfloat16(vx - __bfloat162float(H.b[0]));
                    H.b[1] = __float2bfloat16(vy); L.b[1] = __float2bfloat16(vy - __bfloat162float(H.b[1]));
                    *(uint32_t*)&Ch[(size_t)m * N + n0] = H.u;
                    *(uint32_t*)&Cl[(size_t)m * N + n0] = L.u;
                } else {
                    float2 o; o.x = vx; o.y = vy;
                    *(float2*)&C[(size_t)m * N + n0] = o;
                }
            }
        }
    }
}

// -------------------- span attention (outputs ctx as bf16 hi/lo) --------------------
__global__ __launch_bounds__(256)
void attn_k(const int* __restrict__ span_ids) {
    const int sp = blockIdx.x;
    const int b = sp >> 11;
    const int tid = threadIdx.x;
    __shared__ float sq[Hq];
    __shared__ float sc[NHq][Lq];

    if (!g_mask[sp]) {
        for (int i = tid; i < Hq; i += 256) {
            g_ctx_h[(size_t)sp * Hq + i] = __float2bfloat16(0.f);
            g_ctx_l[(size_t)sp * Hq + i] = __float2bfloat16(0.f);
        }
        return;
    }
    const int start = span_ids[sp * 2 + 0];
    int len = span_ids[sp * 2 + 1] - start;
    if (len > Lq) len = Lq;
    if (len < 1) len = 1;

    for (int i = tid; i < Hq; i += 256) sq[i] = g_q[i];
    __syncthreads();

    const float* kvb = g_KV + (size_t)(b * Tq + start) * (2 * Hq);
    for (int idx = tid; idx < NHq * Lq; idx += 256) {
        const int n = idx >> 5, l = idx & 31;
        float s = -1e30f;
        if (l < len) {
            const float4* kr = (const float4*)(kvb + (size_t)l * (2 * Hq) + n * HD);
            const float4* qr = (const float4*)(sq + n * HD);
            float a = 0.f;
            #pragma unroll
            for (int j = 0; j < 16; j++) {
                float4 k4 = kr[j], q4 = qr[j];
                a = fmaf(k4.x, q4.x, a); a = fmaf(k4.y, q4.y, a);
                a = fmaf(k4.z, q4.z, a); a = fmaf(k4.w, q4.w, a);
            }
            s = a * 0.125f;
        }
        sc[n][l] = s;
    }
    __syncthreads();

    if (tid < NHq) {
        float mx = -1e30f;
        for (int l = 0; l < len; l++) mx = fmaxf(mx, sc[tid][l]);
        float sum = 0.f;
        for (int l = 0; l < Lq; l++) {
            float e = (l < len) ? __expf(sc[tid][l] - mx) : 0.f;
            sc[tid][l] = e; sum += e;
        }
        float inv = 1.f / sum;
        for (int l = 0; l < Lq; l++) sc[tid][l] *= inv;
    }
    __syncthreads();

    const float* vb = kvb + Hq;
    for (int d = tid; d < Hq; d += 256) {
        const int n = d >> 6;
        float a = 0.f;
        for (int l = 0; l < len; l++)
            a = fmaf(sc[n][l], vb[(size_t)l * (2 * Hq) + d], a);
        bf16 h = __float2bfloat16(a);
        g_ctx_h[(size_t)sp * Hq + d] = h;
        g_ctx_l[(size_t)sp * Hq + d] = __float2bfloat16(a - __bfloat162float(h));
    }
}

// -------------------- LayerNorm --------------------
// MODE 0: Y fp32 + Yh/Yl bf16 hi/lo (x1)     MODE 1: Y fp32 * mask (final)
template<int MODE>
__global__ __launch_bounds__(256)
void ln_k(const float* __restrict__ X, const float* __restrict__ g,
          const float* __restrict__ bt, float* __restrict__ Y,
          bf16* __restrict__ Yh, bf16* __restrict__ Yl) {
    const int row = blockIdx.x;
    const int tid = threadIdx.x;
    const float* x = X + (size_t)row * Hq;
    __shared__ float red[8];
    __shared__ float sval;

    float v0 = x[tid], v1 = x[tid + 256], v2 = x[tid + 512];
    float s = v0 + v1 + v2;
    #pragma unroll
    for (int o = 16; o > 0; o >>= 1) s += __shfl_down_sync(0xffffffffu, s, o);
    if ((tid & 31) == 0) red[tid >> 5] = s;
    __syncthreads();
    if (tid == 0) {
        float t = 0.f;
        #pragma unroll
        for (int w = 0; w < 8; w++) t += red[w];
        sval = t * (1.f / Hq);
    }
    __syncthreads();
    const float mean = sval;
    const float d0 = v0 - mean, d1 = v1 - mean, d2 = v2 - mean;
    float vs = d0 * d0 + d1 * d1 + d2 * d2;
    __syncthreads();
    #pragma unroll
    for (int o = 16; o > 0; o >>= 1) vs += __shfl_down_sync(0xffffffffu, vs, o);
    if ((tid & 31) == 0) red[tid >> 5] = vs;
    __syncthreads();
    if (tid == 0) {
        float t = 0.f;
        #pragma unroll
        for (int w = 0; w < 8; w++) t += red[w];
        sval = rsqrtf(t * (1.f / Hq) + 1e-5f);
    }
    __syncthreads();
    const float rstd = sval;
    float m = 1.f;
    if (MODE == 1) m = g_mask[row] ? 1.f : 0.f;
    float* y = Y + (size_t)row * Hq;
    float r0 = (d0 * rstd * g[tid]       + bt[tid])       * m;
    float r1 = (d1 * rstd * g[tid + 256] + bt[tid + 256]) * m;
    float r2 = (d2 * rstd * g[tid + 512] + bt[tid + 512]) * m;
    y[tid] = r0; y[tid + 256] = r1; y[tid + 512] = r2;
    if (MODE == 0) {
        bf16 h0 = __float2bfloat16(r0), h1 = __float2bfloat16(r1), h2 = __float2bfloat16(r2);
        Yh[(size_t)row * Hq + tid]       = h0;
        Yh[(size_t)row * Hq + tid + 256] = h1;
        Yh[(size_t)row * Hq + tid + 512] = h2;
        Yl[(size_t)row * Hq + tid]       = __float2bfloat16(r0 - __bfloat162float(h0));
        Yl[(size_t)row * Hq + tid + 256] = __float2bfloat16(r1 - __bfloat162float(h1));
        Yl[(size_t)row * Hq + tid + 512] = __float2bfloat16(r2 - __bfloat162float(h2));
    }
}

// -------------------- launch --------------------
extern "C" void kernel_launch(void* const* d_in, const int* in_sizes, int n_in,
                              void* d_out, int out_size) {
    const float* token_reps = (const float*)d_in[0];
    const int* span_ids     = (const int*)d_in[1];
    const void* span_masks  = (const void*)d_in[2];
    int k = 3;
    if (n_in >= 16 && in_sizes[3] == 1) k = 4;
    const float* pe          = (const float*)d_in[k + 0];
    const float* dummy_query = (const float*)d_in[k + 1];
    const float* in_proj_w   = (const float*)d_in[k + 2];
    const float* in_proj_b   = (const float*)d_in[k + 3];
    const float* out_proj_w  = (const float*)d_in[k + 4];
    const float* out_proj_b  = (const float*)d_in[k + 5];
    const float* norm_g      = (const float*)d_in[k + 6];
    const float* norm_b      = (const float*)d_in[k + 7];
    const float* ffn_w1      = (const float*)d_in[k + 8];
    const float* ffn_b1      = (const float*)d_in[k + 9];
    const float* ffn_w2      = (const float*)d_in[k + 10];
    const float* ffn_b2      = (const float*)d_in[k + 11];

    float *p_KV, *p_pre1, *p_x1, *p_pre2;
    bf16 *p_tokpe_h, *p_tokpe_l, *p_wkv_h, *p_wkv_l, *p_wout_h, *p_wout_l;
    bf16 *p_w1_h, *p_w1_l, *p_w2_h, *p_w2_l, *p_ctx_h, *p_ctx_l;
    bf16 *p_x1_h, *p_x1_l, *p_h1_h, *p_h1_l;
    cudaGetSymbolAddress((void**)&p_KV, g_KV);
    cudaGetSymbolAddress((void**)&p_pre1, g_pre1);
    cudaGetSymbolAddress((void**)&p_x1, g_x1);
    cudaGetSymbolAddress((void**)&p_pre2, g_pre2);
    cudaGetSymbolAddress((void**)&p_tokpe_h, g_tokpe_h);
    cudaGetSymbolAddress((void**)&p_tokpe_l, g_tokpe_l);
    cudaGetSymbolAddress((void**)&p_wkv_h, g_wkv_h);
    cudaGetSymbolAddress((void**)&p_wkv_l, g_wkv_l);
    cudaGetSymbolAddress((void**)&p_wout_h, g_wout_h);
    cudaGetSymbolAddress((void**)&p_wout_l, g_wout_l);
    cudaGetSymbolAddress((void**)&p_w1_h, g_w1_h);
    cudaGetSymbolAddress((void**)&p_w1_l, g_w1_l);
    cudaGetSymbolAddress((void**)&p_w2_h, g_w2_h);
    cudaGetSymbolAddress((void**)&p_w2_l, g_w2_l);
    cudaGetSymbolAddress((void**)&p_ctx_h, g_ctx_h);
    cudaGetSymbolAddress((void**)&p_ctx_l, g_ctx_l);
    cudaGetSymbolAddress((void**)&p_x1_h, g_x1_h);
    cudaGetSymbolAddress((void**)&p_x1_l, g_x1_l);
    cudaGetSymbolAddress((void**)&p_h1_h, g_h1_h);
    cudaGetSymbolAddress((void**)&p_h1_l, g_h1_l);

    cudaFuncSetAttribute(mma_gemm_k<0>, cudaFuncAttributeMaxDynamicSharedMemorySize, GSMEM_BYTES);
    cudaFuncSetAttribute(mma_gemm_k<1>, cudaFuncAttributeMaxDynamicSharedMemorySize, GSMEM_BYTES);
    cudaFuncSetAttribute(mma_gemm_k<2>, cudaFuncAttributeMaxDynamicSharedMemorySize, GSMEM_BYTES);
    cudaFuncSetAttribute(mma_gemm_k<3>, cudaFuncAttributeMaxDynamicSharedMemorySize, GSMEM_BYTES);

    // 0. canonicalize mask; project q
    mask_conv_k<<<1, 256>>>(span_masks);
    compute_q_k<<<3, 256>>>(dummy_query, in_proj_w, in_proj_b);

    // 1. hi/lo splits of A-side (tok+pe) and all weights
    tokpe_split_k<<<(NTOK * Hq / 4 + 255) / 256, 256>>>(token_reps, pe, p_tokpe_h, p_tokpe_l);
    split_k<<<(2 * Hq * Hq / 4 + 255) / 256, 256>>>(in_proj_w + (size_t)Hq * Hq, p_wkv_h, p_wkv_l, 2 * Hq * Hq / 4);
    split_k<<<(Hq * Hq / 4 + 255) / 256, 256>>>(out_proj_w, p_wout_h, p_wout_l, Hq * Hq / 4);
    split_k<<<(IM * Hq / 4 + 255) / 256, 256>>>(ffn_w1, p_w1_h, p_w1_l, IM * Hq / 4);
    split_k<<<(Hq * IM / 4 + 255) / 256, 256>>>(ffn_w2, p_w2_h, p_w2_l, Hq * IM / 4);

    // 2. KV = (tok+pe) @ Wkv^T + bkv    (1024 x 1536 x 768) -> fp32
    mma_gemm_k<0><<<dim3(12, 8), 256, GSMEM_BYTES>>>(
        p_tokpe_h, p_tokpe_l, p_wkv_h, p_wkv_l,
        in_proj_b + Hq, nullptr, nullptr, p_KV, nullptr, nullptr,
        NTOK, 2 * Hq, Hq);

    // 3. per-span attention -> ctx hi/lo
    attn_k<<<NSPAN, 256>>>(span_ids);

    // 4. pre1 = ctx @ Wout^T + bout + dummy_query   (4096 x 768 x 768)
    mma_gemm_k<1><<<dim3(6, 32), 256, GSMEM_BYTES>>>(
        p_ctx_h, p_ctx_l, p_wout_h, p_wout_l,
        out_proj_b, dummy_query, nullptr, p_pre1, nullptr, nullptr,
        NSPAN, Hq, Hq);

    // 5. x1 = LN(pre1)  (+ hi/lo)
    ln_k<0><<<NSPAN, 256>>>(p_pre1, norm_g, norm_b, p_x1, p_x1_h, p_x1_l);

    // 6. h1 = relu(x1 @ W1^T + b1)   (4096 x 3072 x 768) -> bf16 hi/lo
    mma_gemm_k<2><<<dim3(24, 32), 256, GSMEM_BYTES>>>(
        p_x1_h, p_x1_l, p_w1_h, p_w1_l,
        ffn_b1, nullptr, nullptr, nullptr, p_h1_h, p_h1_l,
        NSPAN, IM, Hq);

    // 7. pre2 = h1 @ W2^T + b2 + x1   (4096 x 768 x 3072)
    mma_gemm_k<3><<<dim3(6, 32), 256, GSMEM_BYTES>>>(
        p_h1_h, p_h1_l, p_w2_h, p_w2_l,
        ffn_b2, nullptr, p_x1, p_pre2, nullptr, nullptr,
        NSPAN, Hq, IM);

    // 8. out = LN(pre2) * mask
    ln_k<1><<<NSPAN, 256>>>(p_pre2, norm_g, norm_b, (float*)d_out, nullptr, nullptr);
}

// round 6
// speedup vs baseline: 2.8112x; 1.0271x over previous
#include <cuda_runtime.h>
#include <cuda_bf16.h>
#include <cstdint>

// Problem constants
#define Bq 2
#define Tq 512
#define Sq 2048
#define Hq 768
#define Lq 32
#define NHq 12
#define HD 64
#define IM 3072
#define NSPAN (Bq*Sq)          // 4096
#define NTOK  (Bq*Tq)          // 1024

typedef __nv_bfloat16 bf16;

// -------------------- device scratch --------------------
__device__ float g_q[Hq];
__device__ float g_KV[(size_t)NTOK * 2 * Hq];
__device__ float g_tokscore[(size_t)NTOK * NHq];
__device__ bf16  g_tokpe_h[(size_t)NTOK * Hq], g_tokpe_l[(size_t)NTOK * Hq];
__device__ bf16  g_wkv_h[(size_t)2 * Hq * Hq], g_wkv_l[(size_t)2 * Hq * Hq];
__device__ bf16  g_wout_h[(size_t)Hq * Hq],   g_wout_l[(size_t)Hq * Hq];
__device__ bf16  g_w1_h[(size_t)IM * Hq],     g_w1_l[(size_t)IM * Hq];
__device__ bf16  g_w2_h[(size_t)Hq * IM],     g_w2_l[(size_t)Hq * IM];
__device__ bf16  g_ctx_h[(size_t)NSPAN * Hq], g_ctx_l[(size_t)NSPAN * Hq];
__device__ float g_pre1[(size_t)NSPAN * Hq];
__device__ float g_x1[(size_t)NSPAN * Hq];
__device__ bf16  g_x1_h[(size_t)NSPAN * Hq],  g_x1_l[(size_t)NSPAN * Hq];
__device__ bf16  g_h1_h[(size_t)NSPAN * IM],  g_h1_l[(size_t)NSPAN * IM];
__device__ float g_pre2[(size_t)NSPAN * Hq];
__device__ unsigned char g_mask[NSPAN];

// -------------------- helpers --------------------
__device__ __forceinline__ uint32_t smem_u32(const void* p) {
    uint32_t a;
    asm("{ .reg .u64 t; cvta.to.shared.u64 t, %1; cvt.u32.u64 %0, t; }" : "=r"(a) : "l"(p));
    return a;
}
#define SW128(o) ((o) ^ (((o) >> 3) & 0x70))

__device__ __forceinline__ void ldm_x4(uint32_t& r0, uint32_t& r1, uint32_t& r2, uint32_t& r3,
                                       uint32_t addr) {
    asm volatile("ldmatrix.sync.aligned.m8n8.x4.shared.b16 {%0,%1,%2,%3}, [%4];"
                 : "=r"(r0), "=r"(r1), "=r"(r2), "=r"(r3) : "r"(addr));
}
__device__ __forceinline__ void mma16816(float* d, const uint32_t* a, const uint32_t* b) {
    asm volatile(
        "mma.sync.aligned.m16n8k16.row.col.f32.bf16.bf16.f32 "
        "{%0,%1,%2,%3}, {%4,%5,%6,%7}, {%8,%9}, {%0,%1,%2,%3};"
        : "+f"(d[0]), "+f"(d[1]), "+f"(d[2]), "+f"(d[3])
        : "r"(a[0]), "r"(a[1]), "r"(a[2]), "r"(a[3]), "r"(b[0]), "r"(b[1]));
}
__device__ __forceinline__ void cp16(uint32_t dst, const void* src) {
    asm volatile("cp.async.cg.shared.global [%0], [%1], 16;" :: "r"(dst), "l"(src));
}
#define CP_COMMIT() asm volatile("cp.async.commit_group;" ::: "memory")
template<int N> __device__ __forceinline__ void cp_wait() {
    asm volatile("cp.async.wait_group %0;" :: "n"(N) : "memory");
}

// -------------------- mask dtype sniffing + conversion --------------------
__global__ void mask_conv_k(const void* __restrict__ raw) {
    __shared__ int notInt, notFloat;
    const int t = threadIdx.x;
    if (t == 0) { notInt = 0; notFloat = 0; }
    __syncthreads();
    {
        const unsigned int v = ((const unsigned int*)raw)[t];
        if (v != 0u && v != 1u) notInt = 1;
        if (v != 0u && v != 0x3F800000u) notFloat = 1;
    }
    __syncthreads();
    const int mode = (!notInt) ? 0 : ((!notFloat) ? 1 : 2);
    for (int i = t; i < NSPAN; i += 256) {
        unsigned char m;
        if (mode == 0)      m = (((const int*)raw)[i] != 0);
        else if (mode == 1) m = (((const float*)raw)[i] != 0.f);
        else                m = (((const unsigned char*)raw)[i] != 0);
        g_mask[i] = m;
    }
}

// -------------------- q projection --------------------
__global__ void compute_q_k(const float* __restrict__ dq,
                            const float* __restrict__ W,
                            const float* __restrict__ b) {
    int i = blockIdx.x * blockDim.x + threadIdx.x;
    if (i < Hq) {
        float s = b[i];
        const float* w = W + (size_t)i * Hq;
        #pragma unroll 8
        for (int h = 0; h < Hq; h++) s = fmaf(dq[h], w[h], s);
        g_q[i] = s;
    }
}

// -------------------- per-token attention scores: tok_scores[t][n] = q_n . K_t_n / 8 ------
__global__ __launch_bounds__(256)
void score_k() {
    const int wid = threadIdx.x >> 5, lane = threadIdx.x & 31;
    const int t = blockIdx.x * 8 + wid;        // 0..1023
    const float* Krow = g_KV + (size_t)t * (2 * Hq);
    #pragma unroll
    for (int n = 0; n < NHq; n++) {
        const int d = n * HD + lane * 2;
        float2 kk = *(const float2*)(Krow + d);
        float2 qq = *(const float2*)(g_q + d);
        float a = kk.x * qq.x + kk.y * qq.y;
        #pragma unroll
        for (int o = 16; o > 0; o >>= 1) a += __shfl_xor_sync(0xffffffffu, a, o);
        if (lane == 0) g_tokscore[t * NHq + n] = a * 0.125f;
    }
}

// -------------------- fp32 -> bf16 hi/lo split kernels --------------------
__global__ void split_k(const float* __restrict__ in, bf16* __restrict__ hi,
                        bf16* __restrict__ lo, int n4) {
    int i = blockIdx.x * 256 + threadIdx.x;
    if (i >= n4) return;
    float4 v = ((const float4*)in)[i];
    union { bf16 b[4]; uint2 u; } H, L;
    H.b[0] = __float2bfloat16(v.x); L.b[0] = __float2bfloat16(v.x - __bfloat162float(H.b[0]));
    H.b[1] = __float2bfloat16(v.y); L.b[1] = __float2bfloat16(v.y - __bfloat162float(H.b[1]));
    H.b[2] = __float2bfloat16(v.z); L.b[2] = __float2bfloat16(v.z - __bfloat162float(H.b[2]));
    H.b[3] = __float2bfloat16(v.w); L.b[3] = __float2bfloat16(v.w - __bfloat162float(H.b[3]));
    ((uint2*)hi)[i] = H.u;
    ((uint2*)lo)[i] = L.u;
}

__global__ void tokpe_split_k(const float* __restrict__ tok, const float* __restrict__ pe,
                              bf16* __restrict__ hi, bf16* __restrict__ lo) {
    int i = blockIdx.x * 256 + threadIdx.x;
    if (i >= NTOK * Hq / 4) return;
    int e = i * 4;
    int pe_e = (e >= Tq * Hq) ? e - Tq * Hq : e;
    float4 a = *(const float4*)(tok + e);
    float4 p = *(const float4*)(pe + pe_e);
    a.x += p.x; a.y += p.y; a.z += p.z; a.w += p.w;
    union { bf16 b[4]; uint2 u; } H, L;
    H.b[0] = __float2bfloat16(a.x); L.b[0] = __float2bfloat16(a.x - __bfloat162float(H.b[0]));
    H.b[1] = __float2bfloat16(a.y); L.b[1] = __float2bfloat16(a.y - __bfloat162float(H.b[1]));
    H.b[2] = __float2bfloat16(a.z); L.b[2] = __float2bfloat16(a.z - __bfloat162float(H.b[2]));
    H.b[3] = __float2bfloat16(a.w); L.b[3] = __float2bfloat16(a.w - __bfloat162float(H.b[3]));
    ((uint2*)hi)[i] = H.u;
    ((uint2*)lo)[i] = L.u;
}

// -------------------- mma.sync bf16-split GEMM: C = A(MxK) * B^T(NxK) + epi --------------------
// 3-stage cp.async pipeline, ONE barrier per chunk, issue interleaved with compute.
// CTA 128x128xBK64; 8 warps (2x4); warp tile 64x32.
// Per stage (64KB): 0=Ah 1=Al 2=Bh 3=Bl; rows of 64 bf16 (128B), SW128.
// EPI: 0 = +bias ; 1 = +bias+resvec ; 2 = relu(+bias) -> bf16 hi/lo ; 3 = +bias+resmat
#define STAGE_BYTES 65536
#define NSTAGE 3
#define GSMEM_BYTES (STAGE_BYTES * NSTAGE)

template<int EPI>
__global__ __launch_bounds__(256, 1)
void mma_gemm_k(const bf16* __restrict__ Ah, const bf16* __restrict__ Al,
                const bf16* __restrict__ Bh, const bf16* __restrict__ Bl,
                const float* __restrict__ bias, const float* __restrict__ resvec,
                const float* __restrict__ resmat,
                float* __restrict__ C, bf16* __restrict__ Ch, bf16* __restrict__ Cl,
                int M, int N, int K) {
    extern __shared__ char sm[];
    const uint32_t sb = smem_u32(sm);
    const int tid = threadIdx.x;
    const int wid = tid >> 5, lane = tid & 31;
    const int wm = wid >> 2;            // 0..1 -> m offset wm*64
    const int wn = wid & 3;             // 0..3 -> n offset wn*32
    const int bm = blockIdx.y * 128, bn = blockIdx.x * 128;

    float acc[4][4][4];
    #pragma unroll
    for (int i = 0; i < 4; i++)
        #pragma unroll
        for (int j = 0; j < 4; j++)
            #pragma unroll
            for (int r = 0; r < 4; r++) acc[i][j][r] = 0.f;

    const int rA_off = (lane & 15);
    const int cqA = lane >> 4;
    const int rB_off = ((lane >> 4) << 3) + (lane & 7);
    const int cqB = (lane >> 3) & 1;

    const int NCH = K >> 6;

    // issue cp.async slots q0..q0+3 (of 16) for chunk c
    auto issue_part = [&](int c, int q0) {
        const int k0 = c << 6;
        const uint32_t sbase = sb + (uint32_t)(c % NSTAGE) * STAGE_BYTES;
        #pragma unroll
        for (int q = q0; q < q0 + 4; q++) {
            const int idx = tid + (q << 8);
            const int t = idx >> 10, r = (idx >> 3) & 127, j = idx & 7;
            const bf16* src;
            if (t == 0)      src = Ah + (size_t)(bm + r) * K + k0 + j * 8;
            else if (t == 1) src = Al + (size_t)(bm + r) * K + k0 + j * 8;
            else if (t == 2) src = Bh + (size_t)(bn + r) * K + k0 + j * 8;
            else             src = Bl + (size_t)(bn + r) * K + k0 + j * 8;
            const uint32_t off = (t << 14) | SW128((r << 7) | (j << 4));
            cp16(sbase + off, src);
        }
    };
    auto issue_chunk = [&](int c) {
        issue_part(c, 0); issue_part(c, 4); issue_part(c, 8); issue_part(c, 12);
        CP_COMMIT();
    };

    issue_chunk(0);
    issue_chunk(1);

    for (int c = 0; c < NCH; c++) {
        cp_wait<1>();
        __syncthreads();            // stage (c-1)%3 now free; chunk c visible to all
        const uint32_t stage = sb + (uint32_t)(c % NSTAGE) * STAGE_BYTES;
        const bool more = (c + 2 < NCH);

        #pragma unroll
        for (int ks = 0; ks < 4; ks++) {
            const int k2 = ks * 2;
            uint32_t ah[4][4], al[4][4];
            #pragma unroll
            for (int mt = 0; mt < 4; mt++) {
                const int row = wm * 64 + mt * 16 + rA_off;
                const uint32_t ph = (uint32_t)((k2 + cqA) ^ (row & 7));
                const uint32_t base = stage + (uint32_t)(row << 7) + (ph << 4);
                ldm_x4(ah[mt][0], ah[mt][1], ah[mt][2], ah[mt][3], base);
                ldm_x4(al[mt][0], al[mt][1], al[mt][2], al[mt][3], base + 16384u);
            }
            uint32_t bh[4][2], bl[4][2];
            #pragma unroll
            for (int p = 0; p < 2; p++) {
                const int row = wn * 32 + p * 16 + rB_off;
                const uint32_t ph = (uint32_t)((k2 + cqB) ^ (row & 7));
                const uint32_t base = stage + 32768u + (uint32_t)(row << 7) + (ph << 4);
                ldm_x4(bh[p*2][0], bh[p*2][1], bh[p*2+1][0], bh[p*2+1][1], base);
                ldm_x4(bl[p*2][0], bl[p*2][1], bl[p*2+1][0], bl[p*2+1][1], base + 16384u);
            }
            if (more) issue_part(c + 2, ks * 4);   // spread LDGSTS through compute
            #pragma unroll
            for (int mt = 0; mt < 4; mt++)
                #pragma unroll
                for (int nt = 0; nt < 4; nt++) {
                    mma16816(acc[mt][nt], ah[mt], bh[nt]);
                    mma16816(acc[mt][nt], ah[mt], bl[nt]);
                    mma16816(acc[mt][nt], al[mt], bh[nt]);
                }
        }
        if (more) CP_COMMIT();
    }

    // epilogue
    const int gq = lane >> 2, tq = lane & 3;
    #pragma unroll
    for (int mt = 0; mt < 4; mt++) {
        #pragma unroll
        for (int nt = 0; nt < 4; nt++) {
            const int n0 = bn + wn * 32 + nt * 8 + tq * 2;
            const float2 bz = *(const float2*)&bias[n0];
            #pragma unroll
            for (int hrow = 0; hrow < 2; hrow++) {
                const int m = bm + wm * 64 + mt * 16 + gq + hrow * 8;
                float vx = acc[mt][nt][hrow * 2 + 0] + bz.x;
                float vy = acc[mt][nt][hrow * 2 + 1] + bz.y;
                if (EPI == 1) {
                    const float2 rv = *(const float2*)&resvec[n0];
                    vx += rv.x; vy += rv.y;
                }
                if (EPI == 3) {
                    const float2 rm = *(const float2*)&resmat[(size_t)m * N + n0];
                    vx += rm.x; vy += rm.y;
                }
                if (EPI == 2) {
                    vx = fmaxf(vx, 0.f); vy = fmaxf(vy, 0.f);
                    union { bf16 b[2]; uint32_t u; } H, L;
                    H.b[0] = __float2bfloat16(vx); L.b[0] = __float2bfloat16(vx - __bfloat162float(H.b[0]));
                    H.b[1] = __float2bfloat16(vy); L.b[1] = __float2bfloat16(vy - __bfloat162float(H.b[1]));
                    *(uint32_t*)&Ch[(size_t)m * N + n0] = H.u;
                    *(uint32_t*)&Cl[(size_t)m * N + n0] = L.u;
                } else {
                    float2 o; o.x = vx; o.y = vy;
                    *(float2*)&C[(size_t)m * N + n0] = o;
                }
            }
        }
    }
}

// -------------------- span attention (V-only traffic; scores precomputed) --------------------
__global__ __launch_bounds__(256)
void attn_k(const int* __restrict__ span_ids) {
    const int sp = blockIdx.x;
    const int b = sp >> 11;
    const int tid = threadIdx.x;
    __shared__ float sc[NHq][Lq];

    if (!g_mask[sp]) {
        for (int i = tid; i < Hq; i += 256) {
            g_ctx_h[(size_t)sp * Hq + i] = __float2bfloat16(0.f);
            g_ctx_l[(size_t)sp * Hq + i] = __float2bfloat16(0.f);
        }
        return;
    }
    const int start = span_ids[sp * 2 + 0];
    int len = span_ids[sp * 2 + 1] - start;
    if (len > Lq) len = Lq;
    if (len < 1) len = 1;
    const int tok0 = b * Tq + start;

    // gather precomputed scores
    for (int idx = tid; idx < NHq * Lq; idx += 256) {
        const int n = idx >> 5, l = idx & 31;
        sc[n][l] = (l < len) ? g_tokscore[(tok0 + l) * NHq + n] : -1e30f;
    }
    __syncthreads();

    if (tid < NHq) {
        float mx = -1e30f;
        for (int l = 0; l < len; l++) mx = fmaxf(mx, sc[tid][l]);
        float sum = 0.f;
        for (int l = 0; l < Lq; l++) {
            float e = (l < len) ? __expf(sc[tid][l] - mx) : 0.f;
            sc[tid][l] = e; sum += e;
        }
        float inv = 1.f / sum;
        for (int l = 0; l < Lq; l++) sc[tid][l] *= inv;
    }
    __syncthreads();

    const float* vb = g_KV + (size_t)tok0 * (2 * Hq) + Hq;   // V part
    for (int d = tid; d < Hq; d += 256) {
        const int n = d >> 6;
        float a = 0.f;
        for (int l = 0; l < len; l++)
            a = fmaf(sc[n][l], vb[(size_t)l * (2 * Hq) + d], a);
        bf16 h = __float2bfloat16(a);
        g_ctx_h[(size_t)sp * Hq + d] = h;
        g_ctx_l[(size_t)sp * Hq + d] = __float2bfloat16(a - __bfloat162float(h));
    }
}

// -------------------- LayerNorm --------------------
// MODE 0: Y fp32 + Yh/Yl bf16 hi/lo (x1)     MODE 1: Y fp32 * mask (final)
template<int MODE>
__global__ __launch_bounds__(256)
void ln_k(const float* __restrict__ X, const float* __restrict__ g,
          const float* __restrict__ bt, float* __restrict__ Y,
          bf16* __restrict__ Yh, bf16* __restrict__ Yl) {
    const int row = blockIdx.x;
    const int tid = threadIdx.x;
    const float* x = X + (size_t)row * Hq;
    __shared__ float red[8];
    __shared__ float sval;

    float v0 = x[tid], v1 = x[tid + 256], v2 = x[tid + 512];
    float s = v0 + v1 + v2;
    #pragma unroll
    for (int o = 16; o > 0; o >>= 1) s += __shfl_down_sync(0xffffffffu, s, o);
    if ((tid & 31) == 0) red[tid >> 5] = s;
    __syncthreads();
    if (tid == 0) {
        float t = 0.f;
        #pragma unroll
        for (int w = 0; w < 8; w++) t += red[w];
        sval = t * (1.f / Hq);
    }
    __syncthreads();
    const float mean = sval;
    const float d0 = v0 - mean, d1 = v1 - mean, d2 = v2 - mean;
    float vs = d0 * d0 + d1 * d1 + d2 * d2;
    __syncthreads();
    #pragma unroll
    for (int o = 16; o > 0; o >>= 1) vs += __shfl_down_sync(0xffffffffu, vs, o);
    if ((tid & 31) == 0) red[tid >> 5] = vs;
    __syncthreads();
    if (tid == 0) {
        float t = 0.f;
        #pragma unroll
        for (int w = 0; w < 8; w++) t += red[w];
        sval = rsqrtf(t * (1.f / Hq) + 1e-5f);
    }
    __syncthreads();
    const float rstd = sval;
    float m = 1.f;
    if (MODE == 1) m = g_mask[row] ? 1.f : 0.f;
    float* y = Y + (size_t)row * Hq;
    float r0 = (d0 * rstd * g[tid]       + bt[tid])       * m;
    float r1 = (d1 * rstd * g[tid + 256] + bt[tid + 256]) * m;
    float r2 = (d2 * rstd * g[tid + 512] + bt[tid + 512]) * m;
    y[tid] = r0; y[tid + 256] = r1; y[tid + 512] = r2;
    if (MODE == 0) {
        bf16 h0 = __float2bfloat16(r0), h1 = __float2bfloat16(r1), h2 = __float2bfloat16(r2);
        Yh[(size_t)row * Hq + tid]       = h0;
        Yh[(size_t)row * Hq + tid + 256] = h1;
        Yh[(size_t)row * Hq + tid + 512] = h2;
        Yl[(size_t)row * Hq + tid]       = __float2bfloat16(r0 - __bfloat162float(h0));
        Yl[(size_t)row * Hq + tid + 256] = __float2bfloat16(r1 - __bfloat162float(h1));
        Yl[(size_t)row * Hq + tid + 512] = __float2bfloat16(r2 - __bfloat162float(h2));
    }
}

// -------------------- launch --------------------
extern "C" void kernel_launch(void* const* d_in, const int* in_sizes, int n_in,
                              void* d_out, int out_size) {
    const float* token_reps = (const float*)d_in[0];
    const int* span_ids     = (const int*)d_in[1];
    const void* span_masks  = (const void*)d_in[2];
    int k = 3;
    if (n_in >= 16 && in_sizes[3] == 1) k = 4;
    const float* pe          = (const float*)d_in[k + 0];
    const float* dummy_query = (const float*)d_in[k + 1];
    const float* in_proj_w   = (const float*)d_in[k + 2];
    const float* in_proj_b   = (const float*)d_in[k + 3];
    const float* out_proj_w  = (const float*)d_in[k + 4];
    const float* out_proj_b  = (const float*)d_in[k + 5];
    const float* norm_g      = (const float*)d_in[k + 6];
    const float* norm_b      = (const float*)d_in[k + 7];
    const float* ffn_w1      = (const float*)d_in[k + 8];
    const float* ffn_b1      = (const float*)d_in[k + 9];
    const float* ffn_w2      = (const float*)d_in[k + 10];
    const float* ffn_b2      = (const float*)d_in[k + 11];

    float *p_KV, *p_pre1, *p_x1, *p_pre2;
    bf16 *p_tokpe_h, *p_tokpe_l, *p_wkv_h, *p_wkv_l, *p_wout_h, *p_wout_l;
    bf16 *p_w1_h, *p_w1_l, *p_w2_h, *p_w2_l, *p_ctx_h, *p_ctx_l;
    bf16 *p_x1_h, *p_x1_l, *p_h1_h, *p_h1_l;
    cudaGetSymbolAddress((void**)&p_KV, g_KV);
    cudaGetSymbolAddress((void**)&p_pre1, g_pre1);
    cudaGetSymbolAddress((void**)&p_x1, g_x1);
    cudaGetSymbolAddress((void**)&p_pre2, g_pre2);
    cudaGetSymbolAddress((void**)&p_tokpe_h, g_tokpe_h);
    cudaGetSymbolAddress((void**)&p_tokpe_l, g_tokpe_l);
    cudaGetSymbolAddress((void**)&p_wkv_h, g_wkv_h);
    cudaGetSymbolAddress((void**)&p_wkv_l, g_wkv_l);
    cudaGetSymbolAddress((void**)&p_wout_h, g_wout_h);
    cudaGetSymbolAddress((void**)&p_wout_l, g_wout_l);
    cudaGetSymbolAddress((void**)&p_w1_h, g_w1_h);
    cudaGetSymbolAddress((void**)&p_w1_l, g_w1_l);
    cudaGetSymbolAddress((void**)&p_w2_h, g_w2_h);
    cudaGetSymbolAddress((void**)&p_w2_l, g_w2_l);
    cudaGetSymbolAddress((void**)&p_ctx_h, g_ctx_h);
    cudaGetSymbolAddress((void**)&p_ctx_l, g_ctx_l);
    cudaGetSymbolAddress((void**)&p_x1_h, g_x1_h);
    cudaGetSymbolAddress((void**)&p_x1_l, g_x1_l);
    cudaGetSymbolAddress((void**)&p_h1_h, g_h1_h);
    cudaGetSymbolAddress((void**)&p_h1_l, g_h1_l);

    cudaFuncSetAttribute(mma_gemm_k<0>, cudaFuncAttributeMaxDynamicSharedMemorySize, GSMEM_BYTES);
    cudaFuncSetAttribute(mma_gemm_k<1>, cudaFuncAttributeMaxDynamicSharedMemorySize, GSMEM_BYTES);
    cudaFuncSetAttribute(mma_gemm_k<2>, cudaFuncAttributeMaxDynamicSharedMemorySize, GSMEM_BYTES);
    cudaFuncSetAttribute(mma_gemm_k<3>, cudaFuncAttributeMaxDynamicSharedMemorySize, GSMEM_BYTES);

    // 0. canonicalize mask; project q
    mask_conv_k<<<1, 256>>>(span_masks);
    compute_q_k<<<3, 256>>>(dummy_query, in_proj_w, in_proj_b);

    // 1. hi/lo splits of A-side (tok+pe) and all weights
    tokpe_split_k<<<(NTOK * Hq / 4 + 255) / 256, 256>>>(token_reps, pe, p_tokpe_h, p_tokpe_l);
    split_k<<<(2 * Hq * Hq / 4 + 255) / 256, 256>>>(in_proj_w + (size_t)Hq * Hq, p_wkv_h, p_wkv_l, 2 * Hq * Hq / 4);
    split_k<<<(Hq * Hq / 4 + 255) / 256, 256>>>(out_proj_w, p_wout_h, p_wout_l, Hq * Hq / 4);
    split_k<<<(IM * Hq / 4 + 255) / 256, 256>>>(ffn_w1, p_w1_h, p_w1_l, IM * Hq / 4);
    split_k<<<(Hq * IM / 4 + 255) / 256, 256>>>(ffn_w2, p_w2_h, p_w2_l, Hq * IM / 4);

    // 2. KV = (tok+pe) @ Wkv^T + bkv    (1024 x 1536 x 768) -> fp32
    mma_gemm_k<0><<<dim3(12, 8), 256, GSMEM_BYTES>>>(
        p_tokpe_h, p_tokpe_l, p_wkv_h, p_wkv_l,
        in_proj_b + Hq, nullptr, nullptr, p_KV, nullptr, nullptr,
        NTOK, 2 * Hq, Hq);

    // 3. per-token scores, then per-span attention -> ctx hi/lo
    score_k<<<NTOK / 8, 256>>>();
    attn_k<<<NSPAN, 256>>>(span_ids);

    // 4. pre1 = ctx @ Wout^T + bout + dummy_query   (4096 x 768 x 768)
    mma_gemm_k<1><<<dim3(6, 32), 256, GSMEM_BYTES>>>(
        p_ctx_h, p_ctx_l, p_wout_h, p_wout_l,
        out_proj_b, dummy_query, nullptr, p_pre1, nullptr, nullptr,
        NSPAN, Hq, Hq);

    // 5. x1 = LN(pre1)  (+ hi/lo)
    ln_k<0><<<NSPAN, 256>>>(p_pre1, norm_g, norm_b, p_x1, p_x1_h, p_x1_l);

    // 6. h1 = relu(x1 @ W1^T + b1)   (4096 x 3072 x 768) -> bf16 hi/lo
    mma_gemm_k<2><<<dim3(24, 32), 256, GSMEM_BYTES>>>(
        p_x1_h, p_x1_l, p_w1_h, p_w1_l,
        ffn_b1, nullptr, nullptr, nullptr, p_h1_h, p_h1_l,
        NSPAN, IM, Hq);

    // 7. pre2 = h1 @ W2^T + b2 + x1   (4096 x 768 x 3072)
    mma_gemm_k<3><<<dim3(6, 32), 256, GSMEM_BYTES>>>(
        p_h1_h, p_h1_l, p_w2_h, p_w2_l,
        ffn_b2, nullptr, p_x1, p_pre2, nullptr, nullptr,
        NSPAN, Hq, IM);

    // 8. out = LN(pre2) * mask
    ln_k<1><<<NSPAN, 256>>>(p_pre2, norm_g, norm_b, (float*)d_out, nullptr, nullptr);
}

// round 7
// speedup vs baseline: 4.2421x; 1.5090x over previous
#include <cuda_runtime.h>
#include <cuda_bf16.h>
#include <cuda_fp16.h>
#include <cstdint>

// Problem constants
#define Bq 2
#define Tq 512
#define Sq 2048
#define Hq 768
#define Lq 32
#define NHq 12
#define HD 64
#define IM 3072
#define NSPAN (Bq*Sq)          // 4096
#define NTOK  (Bq*Tq)          // 1024

typedef __nv_bfloat16 bf16;

// -------------------- device scratch --------------------
__device__ float g_q[Hq];
__device__ float g_KV[(size_t)NTOK * 2 * Hq];
__device__ float g_tokscore[(size_t)NTOK * NHq];
__device__ bf16  g_tokpe_h[(size_t)NTOK * Hq], g_tokpe_l[(size_t)NTOK * Hq];
__device__ bf16  g_wkv_h[(size_t)2 * Hq * Hq], g_wkv_l[(size_t)2 * Hq * Hq];
__device__ bf16  g_wout_h[(size_t)Hq * Hq],   g_wout_l[(size_t)Hq * Hq];
__device__ __half g_w1_f16[(size_t)IM * Hq];
__device__ __half g_w2_f16[(size_t)Hq * IM];
__device__ bf16  g_ctx_h[(size_t)NSPAN * Hq], g_ctx_l[(size_t)NSPAN * Hq];
__device__ float g_pre1[(size_t)NSPAN * Hq];
__device__ float g_x1[(size_t)NSPAN * Hq];
__device__ __half g_x1_f16[(size_t)NSPAN * Hq];
__device__ __half g_h1_f16[(size_t)NSPAN * IM];
__device__ float g_pre2[(size_t)NSPAN * Hq];
__device__ unsigned char g_mask[NSPAN];

// -------------------- helpers --------------------
__device__ __forceinline__ uint32_t smem_u32(const void* p) {
    uint32_t a;
    asm("{ .reg .u64 t; cvta.to.shared.u64 t, %1; cvt.u32.u64 %0, t; }" : "=r"(a) : "l"(p));
    return a;
}
#define SW128(o) ((o) ^ (((o) >> 3) & 0x70))

__device__ __forceinline__ void ldm_x4(uint32_t& r0, uint32_t& r1, uint32_t& r2, uint32_t& r3,
                                       uint32_t addr) {
    asm volatile("ldmatrix.sync.aligned.m8n8.x4.shared.b16 {%0,%1,%2,%3}, [%4];"
                 : "=r"(r0), "=r"(r1), "=r"(r2), "=r"(r3) : "r"(addr));
}
__device__ __forceinline__ void mma16816(float* d, const uint32_t* a, const uint32_t* b) {
    asm volatile(
        "mma.sync.aligned.m16n8k16.row.col.f32.bf16.bf16.f32 "
        "{%0,%1,%2,%3}, {%4,%5,%6,%7}, {%8,%9}, {%0,%1,%2,%3};"
        : "+f"(d[0]), "+f"(d[1]), "+f"(d[2]), "+f"(d[3])
        : "r"(a[0]), "r"(a[1]), "r"(a[2]), "r"(a[3]), "r"(b[0]), "r"(b[1]));
}
__device__ __forceinline__ void mma16816h(float* d, const uint32_t* a, const uint32_t* b) {
    asm volatile(
        "mma.sync.aligned.m16n8k16.row.col.f32.f16.f16.f32 "
        "{%0,%1,%2,%3}, {%4,%5,%6,%7}, {%8,%9}, {%0,%1,%2,%3};"
        : "+f"(d[0]), "+f"(d[1]), "+f"(d[2]), "+f"(d[3])
        : "r"(a[0]), "r"(a[1]), "r"(a[2]), "r"(a[3]), "r"(b[0]), "r"(b[1]));
}
__device__ __forceinline__ void cp16(uint32_t dst, const void* src) {
    asm volatile("cp.async.cg.shared.global [%0], [%1], 16;" :: "r"(dst), "l"(src));
}
#define CP_COMMIT() asm volatile("cp.async.commit_group;" ::: "memory")
template<int N> __device__ __forceinline__ void cp_wait() {
    asm volatile("cp.async.wait_group %0;" :: "n"(N) : "memory");
}

// -------------------- mask dtype sniffing + conversion --------------------
__global__ void mask_conv_k(const void* __restrict__ raw) {
    __shared__ int notInt, notFloat;
    const int t = threadIdx.x;
    if (t == 0) { notInt = 0; notFloat = 0; }
    __syncthreads();
    {
        const unsigned int v = ((const unsigned int*)raw)[t];
        if (v != 0u && v != 1u) notInt = 1;
        if (v != 0u && v != 0x3F800000u) notFloat = 1;
    }
    __syncthreads();
    const int mode = (!notInt) ? 0 : ((!notFloat) ? 1 : 2);
    for (int i = t; i < NSPAN; i += 256) {
        unsigned char m;
        if (mode == 0)      m = (((const int*)raw)[i] != 0);
        else if (mode == 1) m = (((const float*)raw)[i] != 0.f);
        else                m = (((const unsigned char*)raw)[i] != 0);
        g_mask[i] = m;
    }
}

// -------------------- q projection --------------------
__global__ void compute_q_k(const float* __restrict__ dq,
                            const float* __restrict__ W,
                            const float* __restrict__ b) {
    int i = blockIdx.x * blockDim.x + threadIdx.x;
    if (i < Hq) {
        float s = b[i];
        const float* w = W + (size_t)i * Hq;
        #pragma unroll 8
        for (int h = 0; h < Hq; h++) s = fmaf(dq[h], w[h], s);
        g_q[i] = s;
    }
}

// -------------------- per-token attention scores --------------------
__global__ __launch_bounds__(256)
void score_k() {
    const int wid = threadIdx.x >> 5, lane = threadIdx.x & 31;
    const int t = blockIdx.x * 8 + wid;
    const float* Krow = g_KV + (size_t)t * (2 * Hq);
    #pragma unroll
    for (int n = 0; n < NHq; n++) {
        const int d = n * HD + lane * 2;
        float2 kk = *(const float2*)(Krow + d);
        float2 qq = *(const float2*)(g_q + d);
        float a = kk.x * qq.x + kk.y * qq.y;
        #pragma unroll
        for (int o = 16; o > 0; o >>= 1) a += __shfl_xor_sync(0xffffffffu, a, o);
        if (lane == 0) g_tokscore[t * NHq + n] = a * 0.125f;
    }
}

// -------------------- fp32 -> bf16 hi/lo split; fp32 -> fp16 convert --------------------
__global__ void split_k(const float* __restrict__ in, bf16* __restrict__ hi,
                        bf16* __restrict__ lo, int n4) {
    int i = blockIdx.x * 256 + threadIdx.x;
    if (i >= n4) return;
    float4 v = ((const float4*)in)[i];
    union { bf16 b[4]; uint2 u; } H, L;
    H.b[0] = __float2bfloat16(v.x); L.b[0] = __float2bfloat16(v.x - __bfloat162float(H.b[0]));
    H.b[1] = __float2bfloat16(v.y); L.b[1] = __float2bfloat16(v.y - __bfloat162float(H.b[1]));
    H.b[2] = __float2bfloat16(v.z); L.b[2] = __float2bfloat16(v.z - __bfloat162float(H.b[2]));
    H.b[3] = __float2bfloat16(v.w); L.b[3] = __float2bfloat16(v.w - __bfloat162float(H.b[3]));
    ((uint2*)hi)[i] = H.u;
    ((uint2*)lo)[i] = L.u;
}

__global__ void cvt16_k(const float* __restrict__ in, __half* __restrict__ out, int n4) {
    int i = blockIdx.x * 256 + threadIdx.x;
    if (i >= n4) return;
    float4 v = ((const float4*)in)[i];
    __half2 a = __floats2half2_rn(v.x, v.y);
    __half2 b = __floats2half2_rn(v.z, v.w);
    uint2 u; u.x = *(uint32_t*)&a; u.y = *(uint32_t*)&b;
    ((uint2*)out)[i] = u;
}

__global__ void tokpe_split_k(const float* __restrict__ tok, const float* __restrict__ pe,
                              bf16* __restrict__ hi, bf16* __restrict__ lo) {
    int i = blockIdx.x * 256 + threadIdx.x;
    if (i >= NTOK * Hq / 4) return;
    int e = i * 4;
    int pe_e = (e >= Tq * Hq) ? e - Tq * Hq : e;
    float4 a = *(const float4*)(tok + e);
    float4 p = *(const float4*)(pe + pe_e);
    a.x += p.x; a.y += p.y; a.z += p.z; a.w += p.w;
    union { bf16 b[4]; uint2 u; } H, L;
    H.b[0] = __float2bfloat16(a.x); L.b[0] = __float2bfloat16(a.x - __bfloat162float(H.b[0]));
    H.b[1] = __float2bfloat16(a.y); L.b[1] = __float2bfloat16(a.y - __bfloat162float(H.b[1]));
    H.b[2] = __float2bfloat16(a.z); L.b[2] = __float2bfloat16(a.z - __bfloat162float(H.b[2]));
    H.b[3] = __float2bfloat16(a.w); L.b[3] = __float2bfloat16(a.w - __bfloat162float(H.b[3]));
    ((uint2*)hi)[i] = H.u;
    ((uint2*)lo)[i] = L.u;
}

// -------------------- mma.sync GEMM: C = A(MxK) * B^T(NxK) + epi --------------------
// TERMS=3: bf16 hi/lo split, 3 MMAs/kstep.  TERMS=1: fp16 single, 1 MMA/kstep.
// 3-stage cp.async pipeline, one barrier per chunk, loads interleaved with compute.
// EPI: 0 = +bias ; 1 = +bias+resvec ; 2 = relu(+bias) -> fp16 ; 3 = +bias+resmat
#define NSTAGE 3

template<int EPI, int TERMS>
__global__ __launch_bounds__(256, 1)
void mma_gemm_k(const bf16* __restrict__ Ah, const bf16* __restrict__ Al,
                const bf16* __restrict__ Bh, const bf16* __restrict__ Bl,
                const float* __restrict__ bias, const float* __restrict__ resvec,
                const float* __restrict__ resmat,
                float* __restrict__ C, bf16* __restrict__ Ch,
                int M, int N, int K) {
    constexpr int NTILES = (TERMS == 3) ? 4 : 2;
    constexpr uint32_t STB = (uint32_t)NTILES * 16384u;      // stage bytes
    constexpr uint32_t BOFF = (TERMS == 3) ? 32768u : 16384u; // B tile offset in stage
    constexpr int NQ = NTILES * 4;                            // cp16 per thread per chunk
    extern __shared__ char sm[];
    const uint32_t sb = smem_u32(sm);
    const int tid = threadIdx.x;
    const int wid = tid >> 5, lane = tid & 31;
    const int wm = wid >> 2;
    const int wn = wid & 3;
    const int bm = blockIdx.y * 128, bn = blockIdx.x * 128;

    float acc[4][4][4];
    #pragma unroll
    for (int i = 0; i < 4; i++)
        #pragma unroll
        for (int j = 0; j < 4; j++)
            #pragma unroll
            for (int r = 0; r < 4; r++) acc[i][j][r] = 0.f;

    const int rA_off = (lane & 15);
    const int cqA = lane >> 4;
    const int rB_off = ((lane >> 4) << 3) + (lane & 7);
    const int cqB = (lane >> 3) & 1;

    const int NCH = K >> 6;

    // issue one quarter (NQ/4 cp16) of chunk c's loads
    auto issue_part = [&](int c, int part) {
        const int k0 = c << 6;
        const uint32_t sbase = sb + (uint32_t)(c % NSTAGE) * STB;
        #pragma unroll
        for (int q = part * (NQ / 4); q < (part + 1) * (NQ / 4); q++) {
            const int idx = tid + (q << 8);
            const int t = idx >> 10, r = (idx >> 3) & 127, j = idx & 7;
            const bf16* src;
            if (TERMS == 3) {
                if (t == 0)      src = Ah + (size_t)(bm + r) * K + k0 + j * 8;
                else if (t == 1) src = Al + (size_t)(bm + r) * K + k0 + j * 8;
                else if (t == 2) src = Bh + (size_t)(bn + r) * K + k0 + j * 8;
                else             src = Bl + (size_t)(bn + r) * K + k0 + j * 8;
            } else {
                src = (t == 0) ? Ah + (size_t)(bm + r) * K + k0 + j * 8
                               : Bh + (size_t)(bn + r) * K + k0 + j * 8;
            }
            const uint32_t off = ((uint32_t)t << 14) | SW128((r << 7) | (j << 4));
            cp16(sbase + off, src);
        }
    };
    auto issue_chunk = [&](int c) {
        issue_part(c, 0); issue_part(c, 1); issue_part(c, 2); issue_part(c, 3);
        CP_COMMIT();
    };

    issue_chunk(0);
    issue_chunk(1);

    for (int c = 0; c < NCH; c++) {
        cp_wait<1>();
        __syncthreads();
        const uint32_t stage = sb + (uint32_t)(c % NSTAGE) * STB;
        const bool more = (c + 2 < NCH);

        #pragma unroll
        for (int ks = 0; ks < 4; ks++) {
            const int k2 = ks * 2;
            uint32_t ah[4][4], al[4][4];
            #pragma unroll
            for (int mt = 0; mt < 4; mt++) {
                const int row = wm * 64 + mt * 16 + rA_off;
                const uint32_t ph = (uint32_t)((k2 + cqA) ^ (row & 7));
                const uint32_t base = stage + (uint32_t)(row << 7) + (ph << 4);
                ldm_x4(ah[mt][0], ah[mt][1], ah[mt][2], ah[mt][3], base);
                if (TERMS == 3)
                    ldm_x4(al[mt][0], al[mt][1], al[mt][2], al[mt][3], base + 16384u);
            }
            uint32_t bh[4][2], bl[4][2];
            #pragma unroll
            for (int p = 0; p < 2; p++) {
                const int row = wn * 32 + p * 16 + rB_off;
                const uint32_t ph = (uint32_t)((k2 + cqB) ^ (row & 7));
                const uint32_t base = stage + BOFF + (uint32_t)(row << 7) + (ph << 4);
                ldm_x4(bh[p*2][0], bh[p*2][1], bh[p*2+1][0], bh[p*2+1][1], base);
                if (TERMS == 3)
                    ldm_x4(bl[p*2][0], bl[p*2][1], bl[p*2+1][0], bl[p*2+1][1], base + 16384u);
            }
            if (more) issue_part(c + 2, ks);
            #pragma unroll
            for (int mt = 0; mt < 4; mt++)
                #pragma unroll
                for (int nt = 0; nt < 4; nt++) {
                    if (TERMS == 3) {
                        mma16816(acc[mt][nt], ah[mt], bh[nt]);
                        mma16816(acc[mt][nt], ah[mt], bl[nt]);
                        mma16816(acc[mt][nt], al[mt], bh[nt]);
                    } else {
                        mma16816h(acc[mt][nt], ah[mt], bh[nt]);
                    }
                }
        }
        if (more) CP_COMMIT();
    }

    // epilogue
    const int gq = lane >> 2, tq = lane & 3;
    #pragma unroll
    for (int mt = 0; mt < 4; mt++) {
        #pragma unroll
        for (int nt = 0; nt < 4; nt++) {
            const int n0 = bn + wn * 32 + nt * 8 + tq * 2;
            const float2 bz = *(const float2*)&bias[n0];
            #pragma unroll
            for (int hrow = 0; hrow < 2; hrow++) {
                const int m = bm + wm * 64 + mt * 16 + gq + hrow * 8;
                float vx = acc[mt][nt][hrow * 2 + 0] + bz.x;
                float vy = acc[mt][nt][hrow * 2 + 1] + bz.y;
                if (EPI == 1) {
                    const float2 rv = *(const float2*)&resvec[n0];
                    vx += rv.x; vy += rv.y;
                }
                if (EPI == 3) {
                    const float2 rm = *(const float2*)&resmat[(size_t)m * N + n0];
                    vx += rm.x; vy += rm.y;
                }
                if (EPI == 2) {
                    vx = fmaxf(vx, 0.f); vy = fmaxf(vy, 0.f);
                    __half2 hv = __floats2half2_rn(vx, vy);
                    *(uint32_t*)&Ch[(size_t)m * N + n0] = *(uint32_t*)&hv;
                } else {
                    float2 o; o.x = vx; o.y = vy;
                    *(float2*)&C[(size_t)m * N + n0] = o;
                }
            }
        }
    }
}

// -------------------- span attention (V-only traffic; scores precomputed) --------------------
__global__ __launch_bounds__(256)
void attn_k(const int* __restrict__ span_ids) {
    const int sp = blockIdx.x;
    const int b = sp >> 11;
    const int tid = threadIdx.x;
    __shared__ float sc[NHq][Lq];

    if (!g_mask[sp]) {
        for (int i = tid; i < Hq; i += 256) {
            g_ctx_h[(size_t)sp * Hq + i] = __float2bfloat16(0.f);
            g_ctx_l[(size_t)sp * Hq + i] = __float2bfloat16(0.f);
        }
        return;
    }
    const int start = span_ids[sp * 2 + 0];
    int len = span_ids[sp * 2 + 1] - start;
    if (len > Lq) len = Lq;
    if (len < 1) len = 1;
    const int tok0 = b * Tq + start;

    for (int idx = tid; idx < NHq * Lq; idx += 256) {
        const int n = idx >> 5, l = idx & 31;
        sc[n][l] = (l < len) ? g_tokscore[(tok0 + l) * NHq + n] : -1e30f;
    }
    __syncthreads();

    if (tid < NHq) {
        float mx = -1e30f;
        for (int l = 0; l < len; l++) mx = fmaxf(mx, sc[tid][l]);
        float sum = 0.f;
        for (int l = 0; l < Lq; l++) {
            float e = (l < len) ? __expf(sc[tid][l] - mx) : 0.f;
            sc[tid][l] = e; sum += e;
        }
        float inv = 1.f / sum;
        for (int l = 0; l < Lq; l++) sc[tid][l] *= inv;
    }
    __syncthreads();

    const float* vb = g_KV + (size_t)tok0 * (2 * Hq) + Hq;
    for (int d = tid; d < Hq; d += 256) {
        const int n = d >> 6;
        float a = 0.f;
        for (int l = 0; l < len; l++)
            a = fmaf(sc[n][l], vb[(size_t)l * (2 * Hq) + d], a);
        bf16 h = __float2bfloat16(a);
        g_ctx_h[(size_t)sp * Hq + d] = h;
        g_ctx_l[(size_t)sp * Hq + d] = __float2bfloat16(a - __bfloat162float(h));
    }
}

// -------------------- LayerNorm --------------------
// MODE 0: Y fp32 + Y16 fp16 (x1)     MODE 1: Y fp32 * mask (final)
template<int MODE>
__global__ __launch_bounds__(256)
void ln_k(const float* __restrict__ X, const float* __restrict__ g,
          const float* __restrict__ bt, float* __restrict__ Y,
          __half* __restrict__ Y16) {
    const int row = blockIdx.x;
    const int tid = threadIdx.x;
    const float* x = X + (size_t)row * Hq;
    __shared__ float red[8];
    __shared__ float sval;

    float v0 = x[tid], v1 = x[tid + 256], v2 = x[tid + 512];
    float s = v0 + v1 + v2;
    #pragma unroll
    for (int o = 16; o > 0; o >>= 1) s += __shfl_down_sync(0xffffffffu, s, o);
    if ((tid & 31) == 0) red[tid >> 5] = s;
    __syncthreads();
    if (tid == 0) {
        float t = 0.f;
        #pragma unroll
        for (int w = 0; w < 8; w++) t += red[w];
        sval = t * (1.f / Hq);
    }
    __syncthreads();
    const float mean = sval;
    const float d0 = v0 - mean, d1 = v1 - mean, d2 = v2 - mean;
    float vs = d0 * d0 + d1 * d1 + d2 * d2;
    __syncthreads();
    #pragma unroll
    for (int o = 16; o > 0; o >>= 1) vs += __shfl_down_sync(0xffffffffu, vs, o);
    if ((tid & 31) == 0) red[tid >> 5] = vs;
    __syncthreads();
    if (tid == 0) {
        float t = 0.f;
        #pragma unroll
        for (int w = 0; w < 8; w++) t += red[w];
        sval = rsqrtf(t * (1.f / Hq) + 1e-5f);
    }
    __syncthreads();
    const float rstd = sval;
    float m = 1.f;
    if (MODE == 1) m = g_mask[row] ? 1.f : 0.f;
    float* y = Y + (size_t)row * Hq;
    float r0 = (d0 * rstd * g[tid]       + bt[tid])       * m;
    float r1 = (d1 * rstd * g[tid + 256] + bt[tid + 256]) * m;
    float r2 = (d2 * rstd * g[tid + 512] + bt[tid + 512]) * m;
    y[tid] = r0; y[tid + 256] = r1; y[tid + 512] = r2;
    if (MODE == 0) {
        Y16[(size_t)row * Hq + tid]       = __float2half_rn(r0);
        Y16[(size_t)row * Hq + tid + 256] = __float2half_rn(r1);
        Y16[(size_t)row * Hq + tid + 512] = __float2half_rn(r2);
    }
}

// -------------------- launch --------------------
extern "C" void kernel_launch(void* const* d_in, const int* in_sizes, int n_in,
                              void* d_out, int out_size) {
    const float* token_reps = (const float*)d_in[0];
    const int* span_ids     = (const int*)d_in[1];
    const void* span_masks  = (const void*)d_in[2];
    int k = 3;
    if (n_in >= 16 && in_sizes[3] == 1) k = 4;
    const float* pe          = (const float*)d_in[k + 0];
    const float* dummy_query = (const float*)d_in[k + 1];
    const float* in_proj_w   = (const float*)d_in[k + 2];
    const float* in_proj_b   = (const float*)d_in[k + 3];
    const float* out_proj_w  = (const float*)d_in[k + 4];
    const float* out_proj_b  = (const float*)d_in[k + 5];
    const float* norm_g      = (const float*)d_in[k + 6];
    const float* norm_b      = (const float*)d_in[k + 7];
    const float* ffn_w1      = (const float*)d_in[k + 8];
    const float* ffn_b1      = (const float*)d_in[k + 9];
    const float* ffn_w2      = (const float*)d_in[k + 10];
    const float* ffn_b2      = (const float*)d_in[k + 11];

    float *p_KV, *p_pre1, *p_x1, *p_pre2;
    bf16 *p_tokpe_h, *p_tokpe_l, *p_wkv_h, *p_wkv_l, *p_wout_h, *p_wout_l;
    bf16 *p_ctx_h, *p_ctx_l;
    __half *p_w1, *p_w2, *p_x1_16, *p_h1_16;
    cudaGetSymbolAddress((void**)&p_KV, g_KV);
    cudaGetSymbolAddress((void**)&p_pre1, g_pre1);
    cudaGetSymbolAddress((void**)&p_x1, g_x1);
    cudaGetSymbolAddress((void**)&p_pre2, g_pre2);
    cudaGetSymbolAddress((void**)&p_tokpe_h, g_tokpe_h);
    cudaGetSymbolAddress((void**)&p_tokpe_l, g_tokpe_l);
    cudaGetSymbolAddress((void**)&p_wkv_h, g_wkv_h);
    cudaGetSymbolAddress((void**)&p_wkv_l, g_wkv_l);
    cudaGetSymbolAddress((void**)&p_wout_h, g_wout_h);
    cudaGetSymbolAddress((void**)&p_wout_l, g_wout_l);
    cudaGetSymbolAddress((void**)&p_w1, g_w1_f16);
    cudaGetSymbolAddress((void**)&p_w2, g_w2_f16);
    cudaGetSymbolAddress((void**)&p_ctx_h, g_ctx_h);
    cudaGetSymbolAddress((void**)&p_ctx_l, g_ctx_l);
    cudaGetSymbolAddress((void**)&p_x1_16, g_x1_f16);
    cudaGetSymbolAddress((void**)&p_h1_16, g_h1_f16);

    const int SM3 = 4 * 16384 * NSTAGE;   // 196608
    const int SM1 = 2 * 16384 * NSTAGE;   // 98304
    cudaFuncSetAttribute(mma_gemm_k<0, 3>, cudaFuncAttributeMaxDynamicSharedMemorySize, SM3);
    cudaFuncSetAttribute(mma_gemm_k<1, 3>, cudaFuncAttributeMaxDynamicSharedMemorySize, SM3);
    cudaFuncSetAttribute(mma_gemm_k<2, 1>, cudaFuncAttributeMaxDynamicSharedMemorySize, SM1);
    cudaFuncSetAttribute(mma_gemm_k<3, 1>, cudaFuncAttributeMaxDynamicSharedMemorySize, SM1);

    // 0. canonicalize mask; project q
    mask_conv_k<<<1, 256>>>(span_masks);
    compute_q_k<<<3, 256>>>(dummy_query, in_proj_w, in_proj_b);

    // 1. operand prep
    tokpe_split_k<<<(NTOK * Hq / 4 + 255) / 256, 256>>>(token_reps, pe, p_tokpe_h, p_tokpe_l);
    split_k<<<(2 * Hq * Hq / 4 + 255) / 256, 256>>>(in_proj_w + (size_t)Hq * Hq, p_wkv_h, p_wkv_l, 2 * Hq * Hq / 4);
    split_k<<<(Hq * Hq / 4 + 255) / 256, 256>>>(out_proj_w, p_wout_h, p_wout_l, Hq * Hq / 4);
    cvt16_k<<<(IM * Hq / 4 + 255) / 256, 256>>>(ffn_w1, p_w1, IM * Hq / 4);
    cvt16_k<<<(Hq * IM / 4 + 255) / 256, 256>>>(ffn_w2, p_w2, Hq * IM / 4);

    // 2. KV = (tok+pe) @ Wkv^T + bkv    (1024 x 1536 x 768) bf16x3
    mma_gemm_k<0, 3><<<dim3(12, 8), 256, SM3>>>(
        p_tokpe_h, p_tokpe_l, p_wkv_h, p_wkv_l,
        in_proj_b + Hq, nullptr, nullptr, p_KV, nullptr,
        NTOK, 2 * Hq, Hq);

    // 3. per-token scores, then per-span attention -> ctx hi/lo
    score_k<<<NTOK / 8, 256>>>();
    attn_k<<<NSPAN, 256>>>(span_ids);

    // 4. pre1 = ctx @ Wout^T + bout + dummy_query   (4096 x 768 x 768) bf16x3
    mma_gemm_k<1, 3><<<dim3(6, 32), 256, SM3>>>(
        p_ctx_h, p_ctx_l, p_wout_h, p_wout_l,
        out_proj_b, dummy_query, nullptr, p_pre1, nullptr,
        NSPAN, Hq, Hq);

    // 5. x1 = LN(pre1)  (+ fp16)
    ln_k<0><<<NSPAN, 256>>>(p_pre1, norm_g, norm_b, p_x1, p_x1_16);

    // 6. h1 = relu(x1 @ W1^T + b1)   (4096 x 3072 x 768) fp16x1 -> fp16
    mma_gemm_k<2, 1><<<dim3(24, 32), 256, SM1>>>(
        (const bf16*)p_x1_16, nullptr, (const bf16*)p_w1, nullptr,
        ffn_b1, nullptr, nullptr, nullptr, (bf16*)p_h1_16,
        NSPAN, IM, Hq);

    // 7. pre2 = h1 @ W2^T + b2 + x1   (4096 x 768 x 3072) fp16x1
    mma_gemm_k<3, 1><<<dim3(6, 32), 256, SM1>>>(
        (const bf16*)p_h1_16, nullptr, (const bf16*)p_w2, nullptr,
        ffn_b2, nullptr, p_x1, p_pre2, nullptr,
        NSPAN, Hq, IM);

    // 8. out = LN(pre2) * mask
    ln_k<1><<<NSPAN, 256>>>(p_pre2, norm_g, norm_b, (float*)d_out, nullptr);
}

// round 8
// speedup vs baseline: 4.8779x; 1.1499x over previous
#include <cuda_runtime.h>
#include <cuda_bf16.h>
#include <cuda_fp16.h>
#include <cstdint>

// Problem constants
#define Bq 2
#define Tq 512
#define Sq 2048
#define Hq 768
#define Lq 32
#define NHq 12
#define HD 64
#define IM 3072
#define NSPAN (Bq*Sq)          // 4096
#define NTOK  (Bq*Tq)          // 1024

typedef __nv_bfloat16 bf16;

// -------------------- device scratch --------------------
__device__ float g_q[Hq];
__device__ float g_KV[(size_t)NTOK * 2 * Hq];
__device__ float g_tokscore[(size_t)NTOK * NHq];
__device__ bf16  g_tokpe_h[(size_t)NTOK * Hq], g_tokpe_l[(size_t)NTOK * Hq];
__device__ bf16  g_wkv_h[(size_t)2 * Hq * Hq], g_wkv_l[(size_t)2 * Hq * Hq];
__device__ __half g_wout_f16[(size_t)Hq * Hq];
__device__ __half g_w1_f16[(size_t)IM * Hq];
__device__ __half g_w2_f16[(size_t)Hq * IM];
__device__ __half g_ctx_f16[(size_t)NSPAN * Hq];
__device__ float g_pre1[(size_t)NSPAN * Hq];
__device__ float g_x1[(size_t)NSPAN * Hq];
__device__ __half g_x1_f16[(size_t)NSPAN * Hq];
__device__ __half g_h1_f16[(size_t)NSPAN * IM];
__device__ float g_pre2[(size_t)NSPAN * Hq];
__device__ unsigned char g_mask[NSPAN];

// -------------------- helpers --------------------
__device__ __forceinline__ uint32_t smem_u32(const void* p) {
    uint32_t a;
    asm("{ .reg .u64 t; cvta.to.shared.u64 t, %1; cvt.u32.u64 %0, t; }" : "=r"(a) : "l"(p));
    return a;
}
#define SW128(o) ((o) ^ (((o) >> 3) & 0x70))

__device__ __forceinline__ void ldm_x4(uint32_t& r0, uint32_t& r1, uint32_t& r2, uint32_t& r3,
                                       uint32_t addr) {
    asm volatile("ldmatrix.sync.aligned.m8n8.x4.shared.b16 {%0,%1,%2,%3}, [%4];"
                 : "=r"(r0), "=r"(r1), "=r"(r2), "=r"(r3) : "r"(addr));
}
__device__ __forceinline__ void mma16816(float* d, const uint32_t* a, const uint32_t* b) {
    asm volatile(
        "mma.sync.aligned.m16n8k16.row.col.f32.bf16.bf16.f32 "
        "{%0,%1,%2,%3}, {%4,%5,%6,%7}, {%8,%9}, {%0,%1,%2,%3};"
        : "+f"(d[0]), "+f"(d[1]), "+f"(d[2]), "+f"(d[3])
        : "r"(a[0]), "r"(a[1]), "r"(a[2]), "r"(a[3]), "r"(b[0]), "r"(b[1]));
}
__device__ __forceinline__ void mma16816h(float* d, const uint32_t* a, const uint32_t* b) {
    asm volatile(
        "mma.sync.aligned.m16n8k16.row.col.f32.f16.f16.f32 "
        "{%0,%1,%2,%3}, {%4,%5,%6,%7}, {%8,%9}, {%0,%1,%2,%3};"
        : "+f"(d[0]), "+f"(d[1]), "+f"(d[2]), "+f"(d[3])
        : "r"(a[0]), "r"(a[1]), "r"(a[2]), "r"(a[3]), "r"(b[0]), "r"(b[1]));
}
__device__ __forceinline__ void cp16(uint32_t dst, const void* src) {
    asm volatile("cp.async.cg.shared.global [%0], [%1], 16;" :: "r"(dst), "l"(src));
}
#define CP_COMMIT() asm volatile("cp.async.commit_group;" ::: "memory")
template<int N> __device__ __forceinline__ void cp_wait() {
    asm volatile("cp.async.wait_group %0;" :: "n"(N) : "memory");
}

// -------------------- mask dtype sniffing + conversion --------------------
__global__ void mask_conv_k(const void* __restrict__ raw) {
    __shared__ int notInt, notFloat;
    const int t = threadIdx.x;
    if (t == 0) { notInt = 0; notFloat = 0; }
    __syncthreads();
    {
        const unsigned int v = ((const unsigned int*)raw)[t];
        if (v != 0u && v != 1u) notInt = 1;
        if (v != 0u && v != 0x3F800000u) notFloat = 1;
    }
    __syncthreads();
    const int mode = (!notInt) ? 0 : ((!notFloat) ? 1 : 2);
    for (int i = t; i < NSPAN; i += 256) {
        unsigned char m;
        if (mode == 0)      m = (((const int*)raw)[i] != 0);
        else if (mode == 1) m = (((const float*)raw)[i] != 0.f);
        else                m = (((const unsigned char*)raw)[i] != 0);
        g_mask[i] = m;
    }
}

// -------------------- q projection --------------------
__global__ void compute_q_k(const float* __restrict__ dq,
                            const float* __restrict__ W,
                            const float* __restrict__ b) {
    int i = blockIdx.x * blockDim.x + threadIdx.x;
    if (i < Hq) {
        float s = b[i];
        const float* w = W + (size_t)i * Hq;
        #pragma unroll 8
        for (int h = 0; h < Hq; h++) s = fmaf(dq[h], w[h], s);
        g_q[i] = s;
    }
}

// -------------------- per-token attention scores --------------------
__global__ __launch_bounds__(256)
void score_k() {
    const int wid = threadIdx.x >> 5, lane = threadIdx.x & 31;
    const int t = blockIdx.x * 8 + wid;
    const float* Krow = g_KV + (size_t)t * (2 * Hq);
    #pragma unroll
    for (int n = 0; n < NHq; n++) {
        const int d = n * HD + lane * 2;
        float2 kk = *(const float2*)(Krow + d);
        float2 qq = *(const float2*)(g_q + d);
        float a = kk.x * qq.x + kk.y * qq.y;
        #pragma unroll
        for (int o = 16; o > 0; o >>= 1) a += __shfl_xor_sync(0xffffffffu, a, o);
        if (lane == 0) g_tokscore[t * NHq + n] = a * 0.125f;
    }
}

// -------------------- fp32 -> bf16 hi/lo split; fp32 -> fp16 convert --------------------
__global__ void split_k(const float* __restrict__ in, bf16* __restrict__ hi,
                        bf16* __restrict__ lo, int n4) {
    int i = blockIdx.x * 256 + threadIdx.x;
    if (i >= n4) return;
    float4 v = ((const float4*)in)[i];
    union { bf16 b[4]; uint2 u; } H, L;
    H.b[0] = __float2bfloat16(v.x); L.b[0] = __float2bfloat16(v.x - __bfloat162float(H.b[0]));
    H.b[1] = __float2bfloat16(v.y); L.b[1] = __float2bfloat16(v.y - __bfloat162float(H.b[1]));
    H.b[2] = __float2bfloat16(v.z); L.b[2] = __float2bfloat16(v.z - __bfloat162float(H.b[2]));
    H.b[3] = __float2bfloat16(v.w); L.b[3] = __float2bfloat16(v.w - __bfloat162float(H.b[3]));
    ((uint2*)hi)[i] = H.u;
    ((uint2*)lo)[i] = L.u;
}

__global__ void cvt16_k(const float* __restrict__ in, __half* __restrict__ out, int n4) {
    int i = blockIdx.x * 256 + threadIdx.x;
    if (i >= n4) return;
    float4 v = ((const float4*)in)[i];
    __half2 a = __floats2half2_rn(v.x, v.y);
    __half2 b = __floats2half2_rn(v.z, v.w);
    uint2 u; u.x = *(uint32_t*)&a; u.y = *(uint32_t*)&b;
    ((uint2*)out)[i] = u;
}

__global__ void tokpe_split_k(const float* __restrict__ tok, const float* __restrict__ pe,
                              bf16* __restrict__ hi, bf16* __restrict__ lo) {
    int i = blockIdx.x * 256 + threadIdx.x;
    if (i >= NTOK * Hq / 4) return;
    int e = i * 4;
    int pe_e = (e >= Tq * Hq) ? e - Tq * Hq : e;
    float4 a = *(const float4*)(tok + e);
    float4 p = *(const float4*)(pe + pe_e);
    a.x += p.x; a.y += p.y; a.z += p.z; a.w += p.w;
    union { bf16 b[4]; uint2 u; } H, L;
    H.b[0] = __float2bfloat16(a.x); L.b[0] = __float2bfloat16(a.x - __bfloat162float(H.b[0]));
    H.b[1] = __float2bfloat16(a.y); L.b[1] = __float2bfloat16(a.y - __bfloat162float(H.b[1]));
    H.b[2] = __float2bfloat16(a.z); L.b[2] = __float2bfloat16(a.z - __bfloat162float(H.b[2]));
    H.b[3] = __float2bfloat16(a.w); L.b[3] = __float2bfloat16(a.w - __bfloat162float(H.b[3]));
    ((uint2*)hi)[i] = H.u;
    ((uint2*)lo)[i] = L.u;
}

// -------------------- mma.sync GEMM: C = A(MxK) * B^T(NxK) + epi --------------------
// TERMS=3: bf16 hi/lo split (3 MMAs/kstep).  TERMS=1: fp16 single (1 MMA/kstep).
// MTILES: per-warp m16 tiles (4 -> CTA 128 rows, 2 -> CTA 64 rows). CTA N = 128.
// Stage layout (stacked, each tile 1024B-aligned): [Ah (MROWS rows)] [Al?] [Bh (128)] [Bl?]
// EPI: 0 = +bias ; 1 = +bias+resvec ; 2 = relu(+bias) -> fp16 ; 3 = +bias+resmat
#define NSTAGE 3

template<int EPI, int TERMS, int MTILES>
__global__ __launch_bounds__(256, 1)
void mma_gemm_k(const bf16* __restrict__ Ah, const bf16* __restrict__ Al,
                const bf16* __restrict__ Bh, const bf16* __restrict__ Bl,
                const float* __restrict__ bias, const float* __restrict__ resvec,
                const float* __restrict__ resmat,
                float* __restrict__ C, __half* __restrict__ Ch,
                int M, int N, int K) {
    constexpr int MROWS = MTILES * 32;
    constexpr uint32_t A_BYTES = (uint32_t)MROWS * 128u;
    constexpr uint32_t BOFF = (TERMS == 3 ? 2u : 1u) * A_BYTES;
    constexpr uint32_t STB = BOFF + (TERMS == 3 ? 2u : 1u) * 16384u;
    constexpr int NQ = (int)(STB / (16u * 256u));       // cp16 per thread per chunk
    constexpr int ROWS_A2 = 2 * MROWS;                  // end of Al region (TERMS==3)
    extern __shared__ char sm[];
    const uint32_t sb = smem_u32(sm);
    const int tid = threadIdx.x;
    const int wid = tid >> 5, lane = tid & 31;
    const int wm = wid >> 2;
    const int wn = wid & 3;
    const int bm = blockIdx.y * MROWS, bn = blockIdx.x * 128;

    float acc[MTILES][4][4];
    #pragma unroll
    for (int i = 0; i < MTILES; i++)
        #pragma unroll
        for (int j = 0; j < 4; j++)
            #pragma unroll
            for (int r = 0; r < 4; r++) acc[i][j][r] = 0.f;

    const int rA_off = (lane & 15);
    const int cqA = lane >> 4;
    const int rB_off = ((lane >> 4) << 3) + (lane & 7);
    const int cqB = (lane >> 3) & 1;

    const int NCH = K >> 6;

    // issue the q-slots with (q&3)==part for chunk c
    auto issue_part = [&](int c, int part) {
        const int k0 = c << 6;
        const uint32_t sbase = sb + (uint32_t)(c % NSTAGE) * STB;
        #pragma unroll
        for (int q = 0; q < NQ; q++) {
            if ((q & 3) != part) continue;
            const int idx = tid + (q << 8);
            const int rg = idx >> 3, j = idx & 7;
            const bf16* src;
            if (TERMS == 3) {
                if (rg < MROWS)            src = Ah + (size_t)(bm + rg) * K + k0 + j * 8;
                else if (rg < ROWS_A2)     src = Al + (size_t)(bm + rg - MROWS) * K + k0 + j * 8;
                else if (rg < ROWS_A2+128) src = Bh + (size_t)(bn + rg - ROWS_A2) * K + k0 + j * 8;
                else                       src = Bl + (size_t)(bn + rg - ROWS_A2 - 128) * K + k0 + j * 8;
            } else {
                src = (rg < MROWS) ? Ah + (size_t)(bm + rg) * K + k0 + j * 8
                                   : Bh + (size_t)(bn + rg - MROWS) * K + k0 + j * 8;
            }
            cp16(sbase + SW128((uint32_t)idx << 4), src);
        }
    };
    auto issue_chunk = [&](int c) {
        issue_part(c, 0); issue_part(c, 1); issue_part(c, 2); issue_part(c, 3);
        CP_COMMIT();
    };

    issue_chunk(0);
    issue_chunk(1);

    for (int c = 0; c < NCH; c++) {
        cp_wait<1>();
        __syncthreads();
        const uint32_t stage = sb + (uint32_t)(c % NSTAGE) * STB;
        const bool more = (c + 2 < NCH);

        #pragma unroll
        for (int ks = 0; ks < 4; ks++) {
            const int k2 = ks * 2;
            uint32_t ah[MTILES][4], al[MTILES][4];
            #pragma unroll
            for (int mt = 0; mt < MTILES; mt++) {
                const int row = wm * (MTILES * 16) + mt * 16 + rA_off;
                const uint32_t ph = (uint32_t)((k2 + cqA) ^ (row & 7));
                const uint32_t base = stage + (uint32_t)(row << 7) + (ph << 4);
                ldm_x4(ah[mt][0], ah[mt][1], ah[mt][2], ah[mt][3], base);
                if (TERMS == 3)
                    ldm_x4(al[mt][0], al[mt][1], al[mt][2], al[mt][3], base + A_BYTES);
            }
            uint32_t bh[4][2], bl[4][2];
            #pragma unroll
            for (int p = 0; p < 2; p++) {
                const int row = wn * 32 + p * 16 + rB_off;
                const uint32_t ph = (uint32_t)((k2 + cqB) ^ (row & 7));
                const uint32_t base = stage + BOFF + (uint32_t)(row << 7) + (ph << 4);
                ldm_x4(bh[p*2][0], bh[p*2][1], bh[p*2+1][0], bh[p*2+1][1], base);
                if (TERMS == 3)
                    ldm_x4(bl[p*2][0], bl[p*2][1], bl[p*2+1][0], bl[p*2+1][1], base + 16384u);
            }
            if (more) issue_part(c + 2, ks);
            #pragma unroll
            for (int mt = 0; mt < MTILES; mt++)
                #pragma unroll
                for (int nt = 0; nt < 4; nt++) {
                    if (TERMS == 3) {
                        mma16816(acc[mt][nt], ah[mt], bh[nt]);
                        mma16816(acc[mt][nt], ah[mt], bl[nt]);
                        mma16816(acc[mt][nt], al[mt], bh[nt]);
                    } else {
                        mma16816h(acc[mt][nt], ah[mt], bh[nt]);
                    }
                }
        }
        if (more) CP_COMMIT();
    }

    // epilogue
    const int gq = lane >> 2, tq = lane & 3;
    #pragma unroll
    for (int mt = 0; mt < MTILES; mt++) {
        #pragma unroll
        for (int nt = 0; nt < 4; nt++) {
            const int n0 = bn + wn * 32 + nt * 8 + tq * 2;
            const float2 bz = *(const float2*)&bias[n0];
            #pragma unroll
            for (int hrow = 0; hrow < 2; hrow++) {
                const int m = bm + wm * (MTILES * 16) + mt * 16 + gq + hrow * 8;
                float vx = acc[mt][nt][hrow * 2 + 0] + bz.x;
                float vy = acc[mt][nt][hrow * 2 + 1] + bz.y;
                if (EPI == 1) {
                    const float2 rv = *(const float2*)&resvec[n0];
                    vx += rv.x; vy += rv.y;
                }
                if (EPI == 3) {
                    const float2 rm = *(const float2*)&resmat[(size_t)m * N + n0];
                    vx += rm.x; vy += rm.y;
                }
                if (EPI == 2) {
                    vx = fmaxf(vx, 0.f); vy = fmaxf(vy, 0.f);
                    __half2 hv = __floats2half2_rn(vx, vy);
                    *(uint32_t*)&Ch[(size_t)m * N + n0] = *(uint32_t*)&hv;
                } else {
                    float2 o; o.x = vx; o.y = vy;
                    *(float2*)&C[(size_t)m * N + n0] = o;
                }
            }
        }
    }
}

// -------------------- span attention (V-only traffic; scores precomputed; ctx fp16) ------
__global__ __launch_bounds__(256)
void attn_k(const int* __restrict__ span_ids) {
    const int sp = blockIdx.x;
    const int b = sp >> 11;
    const int tid = threadIdx.x;
    __shared__ float sc[NHq][Lq];

    if (!g_mask[sp]) {
        for (int i = tid; i < Hq; i += 256)
            g_ctx_f16[(size_t)sp * Hq + i] = __float2half_rn(0.f);
        return;
    }
    const int start = span_ids[sp * 2 + 0];
    int len = span_ids[sp * 2 + 1] - start;
    if (len > Lq) len = Lq;
    if (len < 1) len = 1;
    const int tok0 = b * Tq + start;

    for (int idx = tid; idx < NHq * Lq; idx += 256) {
        const int n = idx >> 5, l = idx & 31;
        sc[n][l] = (l < len) ? g_tokscore[(tok0 + l) * NHq + n] : -1e30f;
    }
    __syncthreads();

    if (tid < NHq) {
        float mx = -1e30f;
        for (int l = 0; l < len; l++) mx = fmaxf(mx, sc[tid][l]);
        float sum = 0.f;
        for (int l = 0; l < Lq; l++) {
            float e = (l < len) ? __expf(sc[tid][l] - mx) : 0.f;
            sc[tid][l] = e; sum += e;
        }
        float inv = 1.f / sum;
        for (int l = 0; l < Lq; l++) sc[tid][l] *= inv;
    }
    __syncthreads();

    const float* vb = g_KV + (size_t)tok0 * (2 * Hq) + Hq;
    for (int d = tid; d < Hq; d += 256) {
        const int n = d >> 6;
        float a = 0.f;
        for (int l = 0; l < len; l++)
            a = fmaf(sc[n][l], vb[(size_t)l * (2 * Hq) + d], a);
        g_ctx_f16[(size_t)sp * Hq + d] = __float2half_rn(a);
    }
}

// -------------------- LayerNorm --------------------
// MODE 0: Y fp32 + Y16 fp16 (x1)     MODE 1: Y fp32 * mask (final)
template<int MODE>
__global__ __launch_bounds__(256)
void ln_k(const float* __restrict__ X, const float* __restrict__ g,
          const float* __restrict__ bt, float* __restrict__ Y,
          __half* __restrict__ Y16) {
    const int row = blockIdx.x;
    const int tid = threadIdx.x;
    const float* x = X + (size_t)row * Hq;
    __shared__ float red[8];
    __shared__ float sval;

    float v0 = x[tid], v1 = x[tid + 256], v2 = x[tid + 512];
    float s = v0 + v1 + v2;
    #pragma unroll
    for (int o = 16; o > 0; o >>= 1) s += __shfl_down_sync(0xffffffffu, s, o);
    if ((tid & 31) == 0) red[tid >> 5] = s;
    __syncthreads();
    if (tid == 0) {
        float t = 0.f;
        #pragma unroll
        for (int w = 0; w < 8; w++) t += red[w];
        sval = t * (1.f / Hq);
    }
    __syncthreads();
    const float mean = sval;
    const float d0 = v0 - mean, d1 = v1 - mean, d2 = v2 - mean;
    float vs = d0 * d0 + d1 * d1 + d2 * d2;
    __syncthreads();
    #pragma unroll
    for (int o = 16; o > 0; o >>= 1) vs += __shfl_down_sync(0xffffffffu, vs, o);
    if ((tid & 31) == 0) red[tid >> 5] = vs;
    __syncthreads();
    if (tid == 0) {
        float t = 0.f;
        #pragma unroll
        for (int w = 0; w < 8; w++) t += red[w];
        sval = rsqrtf(t * (1.f / Hq) + 1e-5f);
    }
    __syncthreads();
    const float rstd = sval;
    float m = 1.f;
    if (MODE == 1) m = g_mask[row] ? 1.f : 0.f;
    float* y = Y + (size_t)row * Hq;
    float r0 = (d0 * rstd * g[tid]       + bt[tid])       * m;
    float r1 = (d1 * rstd * g[tid + 256] + bt[tid + 256]) * m;
    float r2 = (d2 * rstd * g[tid + 512] + bt[tid + 512]) * m;
    y[tid] = r0; y[tid + 256] = r1; y[tid + 512] = r2;
    if (MODE == 0) {
        Y16[(size_t)row * Hq + tid]       = __float2half_rn(r0);
        Y16[(size_t)row * Hq + tid + 256] = __float2half_rn(r1);
        Y16[(size_t)row * Hq + tid + 512] = __float2half_rn(r2);
    }
}

// -------------------- launch --------------------
extern "C" void kernel_launch(void* const* d_in, const int* in_sizes, int n_in,
                              void* d_out, int out_size) {
    const float* token_reps = (const float*)d_in[0];
    const int* span_ids     = (const int*)d_in[1];
    const void* span_masks  = (const void*)d_in[2];
    int k = 3;
    if (n_in >= 16 && in_sizes[3] == 1) k = 4;
    const float* pe          = (const float*)d_in[k + 0];
    const float* dummy_query = (const float*)d_in[k + 1];
    const float* in_proj_w   = (const float*)d_in[k + 2];
    const float* in_proj_b   = (const float*)d_in[k + 3];
    const float* out_proj_w  = (const float*)d_in[k + 4];
    const float* out_proj_b  = (const float*)d_in[k + 5];
    const float* norm_g      = (const float*)d_in[k + 6];
    const float* norm_b      = (const float*)d_in[k + 7];
    const float* ffn_w1      = (const float*)d_in[k + 8];
    const float* ffn_b1      = (const float*)d_in[k + 9];
    const float* ffn_w2      = (const float*)d_in[k + 10];
    const float* ffn_b2      = (const float*)d_in[k + 11];

    float *p_KV, *p_pre1, *p_x1, *p_pre2;
    bf16 *p_tokpe_h, *p_tokpe_l, *p_wkv_h, *p_wkv_l;
    __half *p_wout, *p_w1, *p_w2, *p_ctx16, *p_x1_16, *p_h1_16;
    cudaGetSymbolAddress((void**)&p_KV, g_KV);
    cudaGetSymbolAddress((void**)&p_pre1, g_pre1);
    cudaGetSymbolAddress((void**)&p_x1, g_x1);
    cudaGetSymbolAddress((void**)&p_pre2, g_pre2);
    cudaGetSymbolAddress((void**)&p_tokpe_h, g_tokpe_h);
    cudaGetSymbolAddress((void**)&p_tokpe_l, g_tokpe_l);
    cudaGetSymbolAddress((void**)&p_wkv_h, g_wkv_h);
    cudaGetSymbolAddress((void**)&p_wkv_l, g_wkv_l);
    cudaGetSymbolAddress((void**)&p_wout, g_wout_f16);
    cudaGetSymbolAddress((void**)&p_w1, g_w1_f16);
    cudaGetSymbolAddress((void**)&p_w2, g_w2_f16);
    cudaGetSymbolAddress((void**)&p_ctx16, g_ctx_f16);
    cudaGetSymbolAddress((void**)&p_x1_16, g_x1_f16);
    cudaGetSymbolAddress((void**)&p_h1_16, g_h1_f16);

    const int SM_T3M4 = 65536 * NSTAGE;   // 196608
    const int SM_T1M4 = 32768 * NSTAGE;   // 98304
    const int SM_T1M2 = 24576 * NSTAGE;   // 73728
    cudaFuncSetAttribute(mma_gemm_k<0, 3, 4>, cudaFuncAttributeMaxDynamicSharedMemorySize, SM_T3M4);
    cudaFuncSetAttribute(mma_gemm_k<1, 1, 2>, cudaFuncAttributeMaxDynamicSharedMemorySize, SM_T1M2);
    cudaFuncSetAttribute(mma_gemm_k<2, 1, 4>, cudaFuncAttributeMaxDynamicSharedMemorySize, SM_T1M4);
    cudaFuncSetAttribute(mma_gemm_k<3, 1, 2>, cudaFuncAttributeMaxDynamicSharedMemorySize, SM_T1M2);

    // 0. canonicalize mask; project q
    mask_conv_k<<<1, 256>>>(span_masks);
    compute_q_k<<<3, 256>>>(dummy_query, in_proj_w, in_proj_b);

    // 1. operand prep
    tokpe_split_k<<<(NTOK * Hq / 4 + 255) / 256, 256>>>(token_reps, pe, p_tokpe_h, p_tokpe_l);
    split_k<<<(2 * Hq * Hq / 4 + 255) / 256, 256>>>(in_proj_w + (size_t)Hq * Hq, p_wkv_h, p_wkv_l, 2 * Hq * Hq / 4);
    cvt16_k<<<(Hq * Hq / 4 + 255) / 256, 256>>>(out_proj_w, p_wout, Hq * Hq / 4);
    cvt16_k<<<(IM * Hq / 4 + 255) / 256, 256>>>(ffn_w1, p_w1, IM * Hq / 4);
    cvt16_k<<<(Hq * IM / 4 + 255) / 256, 256>>>(ffn_w2, p_w2, Hq * IM / 4);

    // 2. KV = (tok+pe) @ Wkv^T + bkv    (1024 x 1536 x 768) bf16x3, CTA 128x128
    mma_gemm_k<0, 3, 4><<<dim3(12, 8), 256, SM_T3M4>>>(
        p_tokpe_h, p_tokpe_l, p_wkv_h, p_wkv_l,
        in_proj_b + Hq, nullptr, nullptr, p_KV, nullptr,
        NTOK, 2 * Hq, Hq);

    // 3. per-token scores, then per-span attention -> ctx fp16
    score_k<<<NTOK / 8, 256>>>();
    attn_k<<<NSPAN, 256>>>(span_ids);

    // 4. pre1 = ctx @ Wout^T + bout + dummy_query   (4096 x 768 x 768) fp16, CTA 64x128
    mma_gemm_k<1, 1, 2><<<dim3(6, 64), 256, SM_T1M2>>>(
        (const bf16*)p_ctx16, nullptr, (const bf16*)p_wout, nullptr,
        out_proj_b, dummy_query, nullptr, p_pre1, nullptr,
        NSPAN, Hq, Hq);

    // 5. x1 = LN(pre1)  (+ fp16)
    ln_k<0><<<NSPAN, 256>>>(p_pre1, norm_g, norm_b, p_x1, p_x1_16);

    // 6. h1 = relu(x1 @ W1^T + b1)   (4096 x 3072 x 768) fp16, CTA 128x128
    mma_gemm_k<2, 1, 4><<<dim3(24, 32), 256, SM_T1M4>>>(
        (const bf16*)p_x1_16, nullptr, (const bf16*)p_w1, nullptr,
        ffn_b1, nullptr, nullptr, nullptr, p_h1_16,
        NSPAN, IM, Hq);

    // 7. pre2 = h1 @ W2^T + b2 + x1   (4096 x 768 x 3072) fp16, CTA 64x128
    mma_gemm_k<3, 1, 2><<<dim3(6, 64), 256, SM_T1M2>>>(
        (const bf16*)p_h1_16, nullptr, (const bf16*)p_w2, nullptr,
        ffn_b2, nullptr, p_x1, p_pre2, nullptr,
        NSPAN, Hq, IM);

    // 8. out = LN(pre2) * mask
    ln_k<1><<<NSPAN, 256>>>(p_pre2, norm_g, norm_b, (float*)d_out, nullptr);
}

// round 9
// speedup vs baseline: 4.9578x; 1.0164x over previous
#include <cuda_runtime.h>
#include <cuda_bf16.h>
#include <cuda_fp16.h>
#include <cstdint>

// Problem constants
#define Bq 2
#define Tq 512
#define Sq 2048
#define Hq 768
#define Lq 32
#define NHq 12
#define HD 64
#define IM 3072
#define NSPAN (Bq*Sq)          // 4096
#define NTOK  (Bq*Tq)          // 1024

typedef __nv_bfloat16 bf16;

// -------------------- device scratch --------------------
__device__ float g_q[Hq];
__device__ float g_KV[(size_t)NTOK * 2 * Hq];
__device__ __half g_V16[(size_t)NTOK * Hq];
__device__ float g_tokscore[(size_t)NTOK * NHq];
__device__ bf16  g_tokpe_h[(size_t)NTOK * Hq], g_tokpe_l[(size_t)NTOK * Hq];
__device__ bf16  g_wkv_h[(size_t)2 * Hq * Hq], g_wkv_l[(size_t)2 * Hq * Hq];
__device__ __half g_wout_f16[(size_t)Hq * Hq];
__device__ __half g_w1_f16[(size_t)IM * Hq];
__device__ __half g_w2_f16[(size_t)Hq * IM];
__device__ __half g_ctx_f16[(size_t)NSPAN * Hq];
__device__ float g_pre1[(size_t)NSPAN * Hq];
__device__ float g_x1[(size_t)NSPAN * Hq];
__device__ __half g_x1_f16[(size_t)NSPAN * Hq];
__device__ __half g_h1_f16[(size_t)NSPAN * IM];
__device__ float g_pre2[(size_t)NSPAN * Hq];
__device__ unsigned char g_mask[NSPAN];

// -------------------- helpers --------------------
__device__ __forceinline__ uint32_t smem_u32(const void* p) {
    uint32_t a;
    asm("{ .reg .u64 t; cvta.to.shared.u64 t, %1; cvt.u32.u64 %0, t; }" : "=r"(a) : "l"(p));
    return a;
}
#define SW128(o) ((o) ^ (((o) >> 3) & 0x70))

__device__ __forceinline__ void ldm_x4(uint32_t& r0, uint32_t& r1, uint32_t& r2, uint32_t& r3,
                                       uint32_t addr) {
    asm volatile("ldmatrix.sync.aligned.m8n8.x4.shared.b16 {%0,%1,%2,%3}, [%4];"
                 : "=r"(r0), "=r"(r1), "=r"(r2), "=r"(r3) : "r"(addr));
}
__device__ __forceinline__ void mma16816(float* d, const uint32_t* a, const uint32_t* b) {
    asm volatile(
        "mma.sync.aligned.m16n8k16.row.col.f32.bf16.bf16.f32 "
        "{%0,%1,%2,%3}, {%4,%5,%6,%7}, {%8,%9}, {%0,%1,%2,%3};"
        : "+f"(d[0]), "+f"(d[1]), "+f"(d[2]), "+f"(d[3])
        : "r"(a[0]), "r"(a[1]), "r"(a[2]), "r"(a[3]), "r"(b[0]), "r"(b[1]));
}
__device__ __forceinline__ void mma16816h(float* d, const uint32_t* a, const uint32_t* b) {
    asm volatile(
        "mma.sync.aligned.m16n8k16.row.col.f32.f16.f16.f32 "
        "{%0,%1,%2,%3}, {%4,%5,%6,%7}, {%8,%9}, {%0,%1,%2,%3};"
        : "+f"(d[0]), "+f"(d[1]), "+f"(d[2]), "+f"(d[3])
        : "r"(a[0]), "r"(a[1]), "r"(a[2]), "r"(a[3]), "r"(b[0]), "r"(b[1]));
}
__device__ __forceinline__ void cp16(uint32_t dst, const void* src) {
    asm volatile("cp.async.cg.shared.global [%0], [%1], 16;" :: "r"(dst), "l"(src));
}
#define CP_COMMIT() asm volatile("cp.async.commit_group;" ::: "memory")
template<int N> __device__ __forceinline__ void cp_wait() {
    asm volatile("cp.async.wait_group %0;" :: "n"(N) : "memory");
}

// -------------------- mask dtype sniffing + conversion --------------------
__global__ void mask_conv_k(const void* __restrict__ raw) {
    __shared__ int notInt, notFloat;
    const int t = threadIdx.x;
    if (t == 0) { notInt = 0; notFloat = 0; }
    __syncthreads();
    {
        const unsigned int v = ((const unsigned int*)raw)[t];
        if (v != 0u && v != 1u) notInt = 1;
        if (v != 0u && v != 0x3F800000u) notFloat = 1;
    }
    __syncthreads();
    const int mode = (!notInt) ? 0 : ((!notFloat) ? 1 : 2);
    for (int i = t; i < NSPAN; i += 256) {
        unsigned char m;
        if (mode == 0)      m = (((const int*)raw)[i] != 0);
        else if (mode == 1) m = (((const float*)raw)[i] != 0.f);
        else                m = (((const unsigned char*)raw)[i] != 0);
        g_mask[i] = m;
    }
}

// -------------------- q projection --------------------
__global__ void compute_q_k(const float* __restrict__ dq,
                            const float* __restrict__ W,
                            const float* __restrict__ b) {
    int i = blockIdx.x * blockDim.x + threadIdx.x;
    if (i < Hq) {
        float s = b[i];
        const float* w = W + (size_t)i * Hq;
        #pragma unroll 8
        for (int h = 0; h < Hq; h++) s = fmaf(dq[h], w[h], s);
        g_q[i] = s;
    }
}

// -------------------- per-token attention scores --------------------
__global__ __launch_bounds__(256)
void score_k() {
    const int wid = threadIdx.x >> 5, lane = threadIdx.x & 31;
    const int t = blockIdx.x * 8 + wid;
    const float* Krow = g_KV + (size_t)t * (2 * Hq);
    #pragma unroll
    for (int n = 0; n < NHq; n++) {
        const int d = n * HD + lane * 2;
        float2 kk = *(const float2*)(Krow + d);
        float2 qq = *(const float2*)(g_q + d);
        float a = kk.x * qq.x + kk.y * qq.y;
        #pragma unroll
        for (int o = 16; o > 0; o >>= 1) a += __shfl_xor_sync(0xffffffffu, a, o);
        if (lane == 0) g_tokscore[t * NHq + n] = a * 0.125f;
    }
}

// -------------------- fused operand prep (grid-stride over 5 regions) --------------------
#define PN0 (NTOK * Hq / 4)                 // tokpe split
#define PN1 (PN0 + 2 * Hq * Hq / 4)         // wkv split
#define PN2 (PN1 + Hq * Hq / 4)             // wout cvt
#define PN3 (PN2 + IM * Hq / 4)             // w1 cvt
#define PN4 (PN3 + Hq * IM / 4)             // w2 cvt

__global__ __launch_bounds__(256)
void prep_k(const float* __restrict__ tok, const float* __restrict__ pe,
            const float* __restrict__ in_proj_w, const float* __restrict__ out_proj_w,
            const float* __restrict__ ffn_w1, const float* __restrict__ ffn_w2) {
    const int i = blockIdx.x * 256 + threadIdx.x;
    if (i >= PN4) return;
    if (i < PN0) {
        const int e = i * 4;
        const int pe_e = (e >= Tq * Hq) ? e - Tq * Hq : e;
        float4 a = *(const float4*)(tok + e);
        float4 p = *(const float4*)(pe + pe_e);
        a.x += p.x; a.y += p.y; a.z += p.z; a.w += p.w;
        union { bf16 b[4]; uint2 u; } H, L;
        H.b[0] = __float2bfloat16(a.x); L.b[0] = __float2bfloat16(a.x - __bfloat162float(H.b[0]));
        H.b[1] = __float2bfloat16(a.y); L.b[1] = __float2bfloat16(a.y - __bfloat162float(H.b[1]));
        H.b[2] = __float2bfloat16(a.z); L.b[2] = __float2bfloat16(a.z - __bfloat162float(H.b[2]));
        H.b[3] = __float2bfloat16(a.w); L.b[3] = __float2bfloat16(a.w - __bfloat162float(H.b[3]));
        ((uint2*)g_tokpe_h)[i] = H.u;
        ((uint2*)g_tokpe_l)[i] = L.u;
    } else if (i < PN1) {
        const int j = i - PN0;
        float4 v = ((const float4*)(in_proj_w + (size_t)Hq * Hq))[j];
        union { bf16 b[4]; uint2 u; } H, L;
        H.b[0] = __float2bfloat16(v.x); L.b[0] = __float2bfloat16(v.x - __bfloat162float(H.b[0]));
        H.b[1] = __float2bfloat16(v.y); L.b[1] = __float2bfloat16(v.y - __bfloat162float(H.b[1]));
        H.b[2] = __float2bfloat16(v.z); L.b[2] = __float2bfloat16(v.z - __bfloat162float(H.b[2]));
        H.b[3] = __float2bfloat16(v.w); L.b[3] = __float2bfloat16(v.w - __bfloat162float(H.b[3]));
        ((uint2*)g_wkv_h)[j] = H.u;
        ((uint2*)g_wkv_l)[j] = L.u;
    } else {
        const float* src;
        __half* dst;
        int j;
        if (i < PN2)      { j = i - PN1; src = out_proj_w; dst = g_wout_f16; }
        else if (i < PN3) { j = i - PN2; src = ffn_w1;     dst = g_w1_f16; }
        else              { j = i - PN3; src = ffn_w2;     dst = g_w2_f16; }
        float4 v = ((const float4*)src)[j];
        __half2 a = __floats2half2_rn(v.x, v.y);
        __half2 b = __floats2half2_rn(v.z, v.w);
        uint2 u; u.x = *(uint32_t*)&a; u.y = *(uint32_t*)&b;
        ((uint2*)dst)[j] = u;
    }
}

// -------------------- mma.sync GEMM: C = A(MxK) * B^T(NxK) + epi --------------------
// TERMS=3: bf16 hi/lo split (3 MMAs/kstep).  TERMS=1: fp16 single (1 MMA/kstep).
// MTILES: per-warp m16 tiles (4 -> CTA 128 rows, 2 -> CTA 64 rows). CTA N = 128.
// EPI: 0 = +bias ; 1 = +bias+resvec ; 2 = relu(+bias) -> fp16 ;
//      3 = +bias+resmat ; 4 = +bias -> fp32, and for n>=Hq also fp16 V copy
#define NSTAGE 3

template<int EPI, int TERMS, int MTILES>
__global__ __launch_bounds__(256, 1)
void mma_gemm_k(const bf16* __restrict__ Ah, const bf16* __restrict__ Al,
                const bf16* __restrict__ Bh, const bf16* __restrict__ Bl,
                const float* __restrict__ bias, const float* __restrict__ resvec,
                const float* __restrict__ resmat,
                float* __restrict__ C, __half* __restrict__ Ch,
                int M, int N, int K) {
    constexpr int MROWS = MTILES * 32;
    constexpr uint32_t A_BYTES = (uint32_t)MROWS * 128u;
    constexpr uint32_t BOFF = (TERMS == 3 ? 2u : 1u) * A_BYTES;
    constexpr uint32_t STB = BOFF + (TERMS == 3 ? 2u : 1u) * 16384u;
    constexpr int NQ = (int)(STB / (16u * 256u));
    constexpr int ROWS_A2 = 2 * MROWS;
    extern __shared__ char sm[];
    const uint32_t sb = smem_u32(sm);
    const int tid = threadIdx.x;
    const int wid = tid >> 5, lane = tid & 31;
    const int wm = wid >> 2;
    const int wn = wid & 3;
    const int bm = blockIdx.y * MROWS, bn = blockIdx.x * 128;

    float acc[MTILES][4][4];
    #pragma unroll
    for (int i = 0; i < MTILES; i++)
        #pragma unroll
        for (int j = 0; j < 4; j++)
            #pragma unroll
            for (int r = 0; r < 4; r++) acc[i][j][r] = 0.f;

    const int rA_off = (lane & 15);
    const int cqA = lane >> 4;
    const int rB_off = ((lane >> 4) << 3) + (lane & 7);
    const int cqB = (lane >> 3) & 1;

    const int NCH = K >> 6;

    auto issue_part = [&](int c, int part) {
        const int k0 = c << 6;
        const uint32_t sbase = sb + (uint32_t)(c % NSTAGE) * STB;
        #pragma unroll
        for (int q = 0; q < NQ; q++) {
            if ((q & 3) != part) continue;
            const int idx = tid + (q << 8);
            const int rg = idx >> 3, j = idx & 7;
            const bf16* src;
            if (TERMS == 3) {
                if (rg < MROWS)            src = Ah + (size_t)(bm + rg) * K + k0 + j * 8;
                else if (rg < ROWS_A2)     src = Al + (size_t)(bm + rg - MROWS) * K + k0 + j * 8;
                else if (rg < ROWS_A2+128) src = Bh + (size_t)(bn + rg - ROWS_A2) * K + k0 + j * 8;
                else                       src = Bl + (size_t)(bn + rg - ROWS_A2 - 128) * K + k0 + j * 8;
            } else {
                src = (rg < MROWS) ? Ah + (size_t)(bm + rg) * K + k0 + j * 8
                                   : Bh + (size_t)(bn + rg - MROWS) * K + k0 + j * 8;
            }
            cp16(sbase + SW128((uint32_t)idx << 4), src);
        }
    };
    auto issue_chunk = [&](int c) {
        issue_part(c, 0); issue_part(c, 1); issue_part(c, 2); issue_part(c, 3);
        CP_COMMIT();
    };

    issue_chunk(0);
    issue_chunk(1);

    for (int c = 0; c < NCH; c++) {
        cp_wait<1>();
        __syncthreads();
        const uint32_t stage = sb + (uint32_t)(c % NSTAGE) * STB;
        const bool more = (c + 2 < NCH);

        #pragma unroll
        for (int ks = 0; ks < 4; ks++) {
            const int k2 = ks * 2;
            uint32_t ah[MTILES][4], al[MTILES][4];
            #pragma unroll
            for (int mt = 0; mt < MTILES; mt++) {
                const int row = wm * (MTILES * 16) + mt * 16 + rA_off;
                const uint32_t ph = (uint32_t)((k2 + cqA) ^ (row & 7));
                const uint32_t base = stage + (uint32_t)(row << 7) + (ph << 4);
                ldm_x4(ah[mt][0], ah[mt][1], ah[mt][2], ah[mt][3], base);
                if (TERMS == 3)
                    ldm_x4(al[mt][0], al[mt][1], al[mt][2], al[mt][3], base + A_BYTES);
            }
            uint32_t bh[4][2], bl[4][2];
            #pragma unroll
            for (int p = 0; p < 2; p++) {
                const int row = wn * 32 + p * 16 + rB_off;
                const uint32_t ph = (uint32_t)((k2 + cqB) ^ (row & 7));
                const uint32_t base = stage + BOFF + (uint32_t)(row << 7) + (ph << 4);
                ldm_x4(bh[p*2][0], bh[p*2][1], bh[p*2+1][0], bh[p*2+1][1], base);
                if (TERMS == 3)
                    ldm_x4(bl[p*2][0], bl[p*2][1], bl[p*2+1][0], bl[p*2+1][1], base + 16384u);
            }
            if (more) issue_part(c + 2, ks);
            #pragma unroll
            for (int mt = 0; mt < MTILES; mt++)
                #pragma unroll
                for (int nt = 0; nt < 4; nt++) {
                    if (TERMS == 3) {
                        mma16816(acc[mt][nt], ah[mt], bh[nt]);
                        mma16816(acc[mt][nt], ah[mt], bl[nt]);
                        mma16816(acc[mt][nt], al[mt], bh[nt]);
                    } else {
                        mma16816h(acc[mt][nt], ah[mt], bh[nt]);
                    }
                }
        }
        if (more) CP_COMMIT();
    }

    // epilogue
    const int gq = lane >> 2, tq = lane & 3;
    #pragma unroll
    for (int mt = 0; mt < MTILES; mt++) {
        #pragma unroll
        for (int nt = 0; nt < 4; nt++) {
            const int n0 = bn + wn * 32 + nt * 8 + tq * 2;
            const float2 bz = *(const float2*)&bias[n0];
            #pragma unroll
            for (int hrow = 0; hrow < 2; hrow++) {
                const int m = bm + wm * (MTILES * 16) + mt * 16 + gq + hrow * 8;
                float vx = acc[mt][nt][hrow * 2 + 0] + bz.x;
                float vy = acc[mt][nt][hrow * 2 + 1] + bz.y;
                if (EPI == 1) {
                    const float2 rv = *(const float2*)&resvec[n0];
                    vx += rv.x; vy += rv.y;
                }
                if (EPI == 3) {
                    const float2 rm = *(const float2*)&resmat[(size_t)m * N + n0];
                    vx += rm.x; vy += rm.y;
                }
                if (EPI == 2) {
                    vx = fmaxf(vx, 0.f); vy = fmaxf(vy, 0.f);
                    __half2 hv = __floats2half2_rn(vx, vy);
                    *(uint32_t*)&Ch[(size_t)m * N + n0] = *(uint32_t*)&hv;
                } else {
                    float2 o; o.x = vx; o.y = vy;
                    *(float2*)&C[(size_t)m * N + n0] = o;
                    if (EPI == 4 && n0 >= Hq) {
                        __half2 hv = __floats2half2_rn(vx, vy);
                        *(uint32_t*)&Ch[(size_t)m * Hq + (n0 - Hq)] = *(uint32_t*)&hv;
                    }
                }
            }
        }
    }
}

// -------------------- span attention (fp16 V; scores precomputed; ctx fp16) ------
__global__ __launch_bounds__(256)
void attn_k(const int* __restrict__ span_ids) {
    const int sp = blockIdx.x;
    const int b = sp >> 11;
    const int tid = threadIdx.x;
    __shared__ float sc[NHq][Lq];

    if (!g_mask[sp]) {
        for (int i = tid; i < Hq; i += 256)
            g_ctx_f16[(size_t)sp * Hq + i] = __float2half_rn(0.f);
        return;
    }
    const int start = span_ids[sp * 2 + 0];
    int len = span_ids[sp * 2 + 1] - start;
    if (len > Lq) len = Lq;
    if (len < 1) len = 1;
    const int tok0 = b * Tq + start;

    for (int idx = tid; idx < NHq * Lq; idx += 256) {
        const int n = idx >> 5, l = idx & 31;
        sc[n][l] = (l < len) ? g_tokscore[(tok0 + l) * NHq + n] : -1e30f;
    }
    __syncthreads();

    if (tid < NHq) {
        float mx = -1e30f;
        for (int l = 0; l < len; l++) mx = fmaxf(mx, sc[tid][l]);
        float sum = 0.f;
        for (int l = 0; l < Lq; l++) {
            float e = (l < len) ? __expf(sc[tid][l] - mx) : 0.f;
            sc[tid][l] = e; sum += e;
        }
        float inv = 1.f / sum;
        for (int l = 0; l < Lq; l++) sc[tid][l] *= inv;
    }
    __syncthreads();

    const __half* vb = g_V16 + (size_t)tok0 * Hq;
    for (int d = tid; d < Hq; d += 256) {
        const int n = d >> 6;
        float a = 0.f;
        for (int l = 0; l < len; l++)
            a = fmaf(sc[n][l], __half2float(vb[(size_t)l * Hq + d]), a);
        g_ctx_f16[(size_t)sp * Hq + d] = __float2half_rn(a);
    }
}

// -------------------- LayerNorm --------------------
// MODE 0: Y fp32 + Y16 fp16 (x1)     MODE 1: Y fp32 * mask (final)
template<int MODE>
__global__ __launch_bounds__(256)
void ln_k(const float* __restrict__ X, const float* __restrict__ g,
          const float* __restrict__ bt, float* __restrict__ Y,
          __half* __restrict__ Y16) {
    const int row = blockIdx.x;
    const int tid = threadIdx.x;
    const float* x = X + (size_t)row * Hq;
    __shared__ float red[8];
    __shared__ float sval;

    float v0 = x[tid], v1 = x[tid + 256], v2 = x[tid + 512];
    float s = v0 + v1 + v2;
    #pragma unroll
    for (int o = 16; o > 0; o >>= 1) s += __shfl_down_sync(0xffffffffu, s, o);
    if ((tid & 31) == 0) red[tid >> 5] = s;
    __syncthreads();
    if (tid == 0) {
        float t = 0.f;
        #pragma unroll
        for (int w = 0; w < 8; w++) t += red[w];
        sval = t * (1.f / Hq);
    }
    __syncthreads();
    const float mean = sval;
    const float d0 = v0 - mean, d1 = v1 - mean, d2 = v2 - mean;
    float vs = d0 * d0 + d1 * d1 + d2 * d2;
    __syncthreads();
    #pragma unroll
    for (int o = 16; o > 0; o >>= 1) vs += __shfl_down_sync(0xffffffffu, vs, o);
    if ((tid & 31) == 0) red[tid >> 5] = vs;
    __syncthreads();
    if (tid == 0) {
        float t = 0.f;
        #pragma unroll
        for (int w = 0; w < 8; w++) t += red[w];
        sval = rsqrtf(t * (1.f / Hq) + 1e-5f);
    }
    __syncthreads();
    const float rstd = sval;
    float m = 1.f;
    if (MODE == 1) m = g_mask[row] ? 1.f : 0.f;
    float* y = Y + (size_t)row * Hq;
    float r0 = (d0 * rstd * g[tid]       + bt[tid])       * m;
    float r1 = (d1 * rstd * g[tid + 256] + bt[tid + 256]) * m;
    float r2 = (d2 * rstd * g[tid + 512] + bt[tid + 512]) * m;
    y[tid] = r0; y[tid + 256] = r1; y[tid + 512] = r2;
    if (MODE == 0) {
        Y16[(size_t)row * Hq + tid]       = __float2half_rn(r0);
        Y16[(size_t)row * Hq + tid + 256] = __float2half_rn(r1);
        Y16[(size_t)row * Hq + tid + 512] = __float2half_rn(r2);
    }
}

// -------------------- launch --------------------
extern "C" void kernel_launch(void* const* d_in, const int* in_sizes, int n_in,
                              void* d_out, int out_size) {
    const float* token_reps = (const float*)d_in[0];
    const int* span_ids     = (const int*)d_in[1];
    const void* span_masks  = (const void*)d_in[2];
    int k = 3;
    if (n_in >= 16 && in_sizes[3] == 1) k = 4;
    const float* pe          = (const float*)d_in[k + 0];
    const float* dummy_query = (const float*)d_in[k + 1];
    const float* in_proj_w   = (const float*)d_in[k + 2];
    const float* in_proj_b   = (const float*)d_in[k + 3];
    const float* out_proj_w  = (const float*)d_in[k + 4];
    const float* out_proj_b  = (const float*)d_in[k + 5];
    const float* norm_g      = (const float*)d_in[k + 6];
    const float* norm_b      = (const float*)d_in[k + 7];
    const float* ffn_w1      = (const float*)d_in[k + 8];
    const float* ffn_b1      = (const float*)d_in[k + 9];
    const float* ffn_w2      = (const float*)d_in[k + 10];
    const float* ffn_b2      = (const float*)d_in[k + 11];

    float *p_KV, *p_pre1, *p_x1, *p_pre2;
    bf16 *p_tokpe_h, *p_tokpe_l, *p_wkv_h, *p_wkv_l;
    __half *p_wout, *p_w1, *p_w2, *p_ctx16, *p_x1_16, *p_h1_16, *p_V16;
    cudaGetSymbolAddress((void**)&p_KV, g_KV);
    cudaGetSymbolAddress((void**)&p_V16, g_V16);
    cudaGetSymbolAddress((void**)&p_pre1, g_pre1);
    cudaGetSymbolAddress((void**)&p_x1, g_x1);
    cudaGetSymbolAddress((void**)&p_pre2, g_pre2);
    cudaGetSymbolAddress((void**)&p_tokpe_h, g_tokpe_h);
    cudaGetSymbolAddress((void**)&p_tokpe_l, g_tokpe_l);
    cudaGetSymbolAddress((void**)&p_wkv_h, g_wkv_h);
    cudaGetSymbolAddress((void**)&p_wkv_l, g_wkv_l);
    cudaGetSymbolAddress((void**)&p_wout, g_wout_f16);
    cudaGetSymbolAddress((void**)&p_w1, g_w1_f16);
    cudaGetSymbolAddress((void**)&p_w2, g_w2_f16);
    cudaGetSymbolAddress((void**)&p_ctx16, g_ctx_f16);
    cudaGetSymbolAddress((void**)&p_x1_16, g_x1_f16);
    cudaGetSymbolAddress((void**)&p_h1_16, g_h1_f16);

    const int SM_T3M4 = 65536 * NSTAGE;   // 196608
    const int SM_T1M4 = 32768 * NSTAGE;   // 98304
    const int SM_T1M2 = 24576 * NSTAGE;   // 73728
    cudaFuncSetAttribute(mma_gemm_k<4, 3, 4>, cudaFuncAttributeMaxDynamicSharedMemorySize, SM_T3M4);
    cudaFuncSetAttribute(mma_gemm_k<1, 1, 2>, cudaFuncAttributeMaxDynamicSharedMemorySize, SM_T1M2);
    cudaFuncSetAttribute(mma_gemm_k<2, 1, 4>, cudaFuncAttributeMaxDynamicSharedMemorySize, SM_T1M4);
    cudaFuncSetAttribute(mma_gemm_k<3, 1, 2>, cudaFuncAttributeMaxDynamicSharedMemorySize, SM_T1M2);

    // 0. canonicalize mask; project q; fused operand prep
    mask_conv_k<<<1, 256>>>(span_masks);
    compute_q_k<<<3, 256>>>(dummy_query, in_proj_w, in_proj_b);
    prep_k<<<(PN4 + 255) / 256, 256>>>(token_reps, pe, in_proj_w, out_proj_w, ffn_w1, ffn_w2);

    // 2. KV = (tok+pe) @ Wkv^T + bkv  (1024 x 1536 x 768) bf16x3; also emits fp16 V
    mma_gemm_k<4, 3, 4><<<dim3(12, 8), 256, SM_T3M4>>>(
        p_tokpe_h, p_tokpe_l, p_wkv_h, p_wkv_l,
        in_proj_b + Hq, nullptr, nullptr, p_KV, p_V16,
        NTOK, 2 * Hq, Hq);

    // 3. per-token scores, then per-span attention -> ctx fp16
    score_k<<<NTOK / 8, 256>>>();
    attn_k<<<NSPAN, 256>>>(span_ids);

    // 4. pre1 = ctx @ Wout^T + bout + dummy_query   (4096 x 768 x 768) fp16, CTA 64x128
    mma_gemm_k<1, 1, 2><<<dim3(6, 64), 256, SM_T1M2>>>(
        (const bf16*)p_ctx16, nullptr, (const bf16*)p_wout, nullptr,
        out_proj_b, dummy_query, nullptr, p_pre1, nullptr,
        NSPAN, Hq, Hq);

    // 5. x1 = LN(pre1)  (+ fp16)
    ln_k<0><<<NSPAN, 256>>>(p_pre1, norm_g, norm_b, p_x1, p_x1_16);

    // 6. h1 = relu(x1 @ W1^T + b1)   (4096 x 3072 x 768) fp16, CTA 128x128
    mma_gemm_k<2, 1, 4><<<dim3(24, 32), 256, SM_T1M4>>>(
        (const bf16*)p_x1_16, nullptr, (const bf16*)p_w1, nullptr,
        ffn_b1, nullptr, nullptr, nullptr, p_h1_16,
        NSPAN, IM, Hq);

    // 7. pre2 = h1 @ W2^T + b2 + x1   (4096 x 768 x 3072) fp16, CTA 64x128
    mma_gemm_k<3, 1, 2><<<dim3(6, 64), 256, SM_T1M2>>>(
        (const bf16*)p_h1_16, nullptr, (const bf16*)p_w2, nullptr,
        ffn_b2, nullptr, p_x1, p_pre2, nullptr,
        NSPAN, Hq, IM);

    // 8. out = LN(pre2) * mask
    ln_k<1><<<NSPAN, 256>>>(p_pre2, norm_g, norm_b, (float*)d_out, nullptr);
}